// round 8
// baseline (speedup 1.0000x reference)
#include <cuda_runtime.h>
#include <cuda.h>
#include <cuda_bf16.h>
#include <cstdint>

typedef unsigned long long ull;

#define BSZ    2
#define SEQ    2048
#define EMBED  1024
#define HEADS  16
#define HDIM   64
#define NTOK   (BSZ*SEQ)

// ---------------- scratch (no allocations allowed) ----------------
__device__ __nv_bfloat16 g_AQh[NTOK*EMBED];
__device__ __nv_bfloat16 g_AQl[NTOK*EMBED];
__device__ __nv_bfloat16 g_AKh[NTOK*EMBED];
__device__ __nv_bfloat16 g_AKl[NTOK*EMBED];
__device__ __nv_bfloat16 g_AVh[NTOK*EMBED];
__device__ __nv_bfloat16 g_AVl[NTOK*EMBED];
__device__ __nv_bfloat16 g_Qh[NTOK*EMBED];
__device__ __nv_bfloat16 g_Ql[NTOK*EMBED];
__device__ __nv_bfloat16 g_Kh[NTOK*EMBED];
__device__ __nv_bfloat16 g_Kl[NTOK*EMBED];
__device__ __nv_bfloat16 g_Vh[NTOK*EMBED];
__device__ __nv_bfloat16 g_Vl[NTOK*EMBED];
__device__ __nv_bfloat16 g_WQh[EMBED*EMBED];
__device__ __nv_bfloat16 g_WQl[EMBED*EMBED];
__device__ __nv_bfloat16 g_WKh[EMBED*EMBED];
__device__ __nv_bfloat16 g_WKl[EMBED*EMBED];
__device__ __nv_bfloat16 g_WVh[EMBED*EMBED];
__device__ __nv_bfloat16 g_WVl[EMBED*EMBED];
__device__ __nv_bfloat16 g_WOh[EMBED*EMBED];
__device__ __nv_bfloat16 g_WOl[EMBED*EMBED];

// ---------------- PTX helpers (all non-'a' features) ---------------
__device__ __forceinline__ uint32_t smem_u32(const void* p) {
    uint32_t a;
    asm("{ .reg .u64 t; cvta.to.shared.u64 t, %1; cvt.u32.u64 %0, t; }" : "=r"(a) : "l"(p));
    return a;
}

#define MBARRIER_INIT(mbar, cnt) \
    asm volatile("mbarrier.init.shared.b64 [%0], %1;" :: "r"(mbar), "r"(cnt) : "memory")
#define MBARRIER_EXPECT_TX(mbar, bytes) \
    asm volatile("mbarrier.arrive.expect_tx.shared.b64 _, [%0], %1;" :: "r"(mbar), "r"(bytes) : "memory")
#define MBARRIER_ARRIVE(mbar) \
    asm volatile("mbarrier.arrive.release.cta.shared.b64 _, [%0];" :: "r"(mbar) : "memory")

#define MBARRIER_WAIT_PARITY(mbar_addr, phase_parity) do {                                   \
    uint32_t _mbar = (uint32_t)(mbar_addr);                                                  \
    uint32_t _par  = (uint32_t)(phase_parity);                                               \
    uint32_t _done;                                                                          \
    asm volatile("{\n\t.reg .pred p;\n\t"                                                    \
        "mbarrier.try_wait.parity.acquire.cta.shared::cta.b64 p, [%1], %2;\n\t"              \
        "selp.b32 %0, 1, 0, p;\n\t}"                                                         \
        : "=r"(_done) : "r"(_mbar), "r"(_par) : "memory");                                   \
    if (!_done) {                                                                            \
        asm volatile("{\n\t.reg .pred P1;\n\t"                                               \
            "WL_%=:\n\t"                                                                     \
            "mbarrier.try_wait.parity.acquire.cta.shared::cta.b64 P1, [%0], %1, 0x989680;\n\t" \
            "@P1 bra.uni WD_%=;\n\t"                                                         \
            "bra.uni WL_%=;\n\t"                                                             \
            "WD_%=:\n\t}"                                                                    \
            :: "r"(_mbar), "r"(_par) : "memory");                                            \
    }                                                                                        \
} while (0)

__device__ __forceinline__ void tma2d(uint32_t dst, const CUtensorMap* map,
                                      int x, int y, uint32_t mbar) {
    asm volatile(
        "cp.async.bulk.tensor.2d.shared::cta.global.tile.mbarrier::complete_tx::bytes "
        "[%0], [%1, {%2, %3}], [%4];"
        :: "r"(dst), "l"(map), "r"(x), "r"(y), "r"(mbar) : "memory");
}

#define LDSM4(r, addr)                                                           \
    asm volatile("ldmatrix.sync.aligned.m8n8.x4.shared.b16 {%0,%1,%2,%3}, [%4];" \
        : "=r"((r)[0]), "=r"((r)[1]), "=r"((r)[2]), "=r"((r)[3]) : "r"(addr))

#define LDSM4T(r, addr)                                                          \
    asm volatile("ldmatrix.sync.aligned.m8n8.x4.trans.shared.b16 {%0,%1,%2,%3}, [%4];" \
        : "=r"((r)[0]), "=r"((r)[1]), "=r"((r)[2]), "=r"((r)[3]) : "r"(addr))

#define MMA16816(d, a, b0v, b1v)                                                 \
    asm volatile("mma.sync.aligned.m16n8k16.row.col.f32.bf16.bf16.f32 "          \
        "{%0,%1,%2,%3}, {%4,%5,%6,%7}, {%8,%9}, {%0,%1,%2,%3};"                  \
        : "+f"((d)[0]), "+f"((d)[1]), "+f"((d)[2]), "+f"((d)[3])                 \
        : "r"((a)[0]), "r"((a)[1]), "r"((a)[2]), "r"((a)[3]), "r"(b0v), "r"(b1v))

__device__ __forceinline__ uint32_t swz128(uint32_t o) {  // Swizzle<3,4,3>
    return o ^ ((o >> 3) & 0x70u);
}
__device__ __forceinline__ float ex2f(float x) {
    float y; asm("ex2.approx.ftz.f32 %0, %1;" : "=f"(y) : "f"(x)); return y;
}
__device__ __forceinline__ uint32_t prmt7632(uint32_t a, uint32_t b) {
    uint32_t d; asm("prmt.b32 %0, %1, %2, 0x7632;" : "=r"(d) : "r"(a), "r"(b)); return d;
}
__device__ __forceinline__ uint32_t cvt_bf16x2(float hi, float lo) {
    uint32_t d; asm("cvt.rn.bf16x2.f32 %0, %1, %2;" : "=r"(d) : "f"(hi), "f"(lo)); return d;
}
__device__ __forceinline__ float truncbf(float x) {
    return __uint_as_float(__float_as_uint(x) & 0xffff0000u);
}

// ===================================================================
// fused split: 7 tensors, fp32 -> bf16 hi + bf16 lo
// ===================================================================
struct SplitJob { const float* src; __nv_bfloat16* hi; __nv_bfloat16* lo; int nblk; };
struct SplitJobs { SplitJob j[7]; };

__global__ __launch_bounds__(256)
void split_all(const SplitJobs J)
{
    SplitJob jb = J.j[blockIdx.y];
    if ((int)blockIdx.x >= jb.nblk) return;
    int i = (blockIdx.x * 256 + threadIdx.x) * 4;
    float4 v = *(const float4*)(jb.src + i);
    __nv_bfloat16 h0 = __float2bfloat16_rn(v.x);
    __nv_bfloat16 h1 = __float2bfloat16_rn(v.y);
    __nv_bfloat16 h2 = __float2bfloat16_rn(v.z);
    __nv_bfloat16 h3 = __float2bfloat16_rn(v.w);
    __nv_bfloat16 l0 = __float2bfloat16_rn(v.x - __bfloat162float(h0));
    __nv_bfloat16 l1 = __float2bfloat16_rn(v.y - __bfloat162float(h1));
    __nv_bfloat16 l2 = __float2bfloat16_rn(v.z - __bfloat162float(h2));
    __nv_bfloat16 l3 = __float2bfloat16_rn(v.w - __bfloat162float(h3));
    ushort4 hv = make_ushort4(*(unsigned short*)&h0, *(unsigned short*)&h1,
                              *(unsigned short*)&h2, *(unsigned short*)&h3);
    ushort4 lv = make_ushort4(*(unsigned short*)&l0, *(unsigned short*)&l1,
                              *(unsigned short*)&l2, *(unsigned short*)&l3);
    *(ushort4*)(jb.hi + i) = hv;
    *(ushort4*)(jb.lo + i) = lv;
}

// ===================================================================
// GEMM (NT, bf16x3): 128x64x64 CTA tile, 2-stage TMA, 2 CTAs/SM.
// ===================================================================
#define GK      1024
#define GN      1024
#define GBN     64
#define GBK     64
#define GNK     (GK/GBK)
#define GS      2
#define TILE_A  16384
#define TILE_W  8192
#define STAGE_B (2*TILE_A + 2*TILE_W)   // 49152
#define GEMM_SMEM (GS*STAGE_B + 1024)

struct QkvMaps {
    CUtensorMap aH[3];
    CUtensorMap aL[3];
    CUtensorMap wH[3];
    CUtensorMap wL[3];
};

__device__ __forceinline__ void gemm_mainloop(
    const CUtensorMap* tAh, const CUtensorMap* tAl,
    const CUtensorMap* tBh, const CUtensorMap* tBl,
    int bm, int bn, uint32_t tile0, uint32_t full0, uint32_t emt0,
    int tid, int lane, float acc[2][4][4],
    uint32_t aOffBase, uint32_t bOffBase)
{
    if (tid == 0) {
#pragma unroll
        for (int s = 0; s < GS; s++) {
            uint32_t st = tile0 + s * STAGE_B;
            MBARRIER_EXPECT_TX(full0 + 8 * s, STAGE_B);
            int k0 = s * GBK;
            tma2d(st,                       tAh, k0, bm, full0 + 8 * s);
            tma2d(st + TILE_A,              tAl, k0, bm, full0 + 8 * s);
            tma2d(st + 2 * TILE_A,          tBh, k0, bn, full0 + 8 * s);
            tma2d(st + 2 * TILE_A + TILE_W, tBl, k0, bn, full0 + 8 * s);
        }
    }

    for (int i = 0; i < GNK; i++) {
        const int s  = i % GS;
        const int ph = (i / GS) & 1;
        MBARRIER_WAIT_PARITY(full0 + 8 * s, ph);

        const uint32_t st = tile0 + s * STAGE_B;
        const uint32_t aH = st, aL = st + TILE_A;
        const uint32_t bH = st + 2 * TILE_A, bL = st + 2 * TILE_A + TILE_W;

#pragma unroll
        for (int ks = 0; ks < 4; ks++) {
            const uint32_t kb = (uint32_t)ks * 32;
            uint32_t ah[2][4], al[2][4];
#pragma unroll
            for (int sub = 0; sub < 2; sub++) {
                uint32_t off = swz128(aOffBase + (uint32_t)sub * 16 * 128 + kb);
                LDSM4(ah[sub], aH + off);
                LDSM4(al[sub], aL + off);
            }
            uint32_t bh[2][4], bl[2][4];
#pragma unroll
            for (int nb = 0; nb < 2; nb++) {
                uint32_t off = swz128(bOffBase + (uint32_t)nb * 16 * 128 + kb);
                LDSM4(bh[nb], bH + off);
                LDSM4(bl[nb], bL + off);
            }
            // pass hh
            MMA16816(acc[0][0], ah[0], bh[0][0], bh[0][1]);
            MMA16816(acc[0][1], ah[0], bh[0][2], bh[0][3]);
            MMA16816(acc[0][2], ah[0], bh[1][0], bh[1][1]);
            MMA16816(acc[0][3], ah[0], bh[1][2], bh[1][3]);
            MMA16816(acc[1][0], ah[1], bh[0][0], bh[0][1]);
            MMA16816(acc[1][1], ah[1], bh[0][2], bh[0][3]);
            MMA16816(acc[1][2], ah[1], bh[1][0], bh[1][1]);
            MMA16816(acc[1][3], ah[1], bh[1][2], bh[1][3]);
            // pass hl
            MMA16816(acc[0][0], ah[0], bl[0][0], bl[0][1]);
            MMA16816(acc[0][1], ah[0], bl[0][2], bl[0][3]);
            MMA16816(acc[0][2], ah[0], bl[1][0], bl[1][1]);
            MMA16816(acc[0][3], ah[0], bl[1][2], bl[1][3]);
            MMA16816(acc[1][0], ah[1], bl[0][0], bl[0][1]);
            MMA16816(acc[1][1], ah[1], bl[0][2], bl[0][3]);
            MMA16816(acc[1][2], ah[1], bl[1][0], bl[1][1]);
            MMA16816(acc[1][3], ah[1], bl[1][2], bl[1][3]);
            // pass lh
            MMA16816(acc[0][0], al[0], bh[0][0], bh[0][1]);
            MMA16816(acc[0][1], al[0], bh[0][2], bh[0][3]);
            MMA16816(acc[0][2], al[0], bh[1][0], bh[1][1]);
            MMA16816(acc[0][3], al[0], bh[1][2], bh[1][3]);
            MMA16816(acc[1][0], al[1], bh[0][0], bh[0][1]);
            MMA16816(acc[1][1], al[1], bh[0][2], bh[0][3]);
            MMA16816(acc[1][2], al[1], bh[1][0], bh[1][1]);
            MMA16816(acc[1][3], al[1], bh[1][2], bh[1][3]);
        }
        if (lane == 0) MBARRIER_ARRIVE(emt0 + 8 * s);

        if (i + GS < GNK && tid == 0) {
            MBARRIER_WAIT_PARITY(emt0 + 8 * s, ph);
            MBARRIER_EXPECT_TX(full0 + 8 * s, STAGE_B);
            int k0 = (i + GS) * GBK;
            tma2d(st,                       tAh, k0, bm, full0 + 8 * s);
            tma2d(st + TILE_A,              tAl, k0, bm, full0 + 8 * s);
            tma2d(st + 2 * TILE_A,          tBh, k0, bn, full0 + 8 * s);
            tma2d(st + 2 * TILE_A + TILE_W, tBl, k0, bn, full0 + 8 * s);
        }
    }
}

// fused QKV projection
__global__ __launch_bounds__(256, 2)
void gemm_qkv(const __grid_constant__ QkvMaps M,
              const float* __restrict__ bq, const float* __restrict__ bk,
              const float* __restrict__ bv,
              __nv_bfloat16* __restrict__ Qh, __nv_bfloat16* __restrict__ Ql,
              __nv_bfloat16* __restrict__ Kh, __nv_bfloat16* __restrict__ Kl,
              __nv_bfloat16* __restrict__ Vh, __nv_bfloat16* __restrict__ Vl)
{
    extern __shared__ uint8_t dsm[];
    __shared__ __align__(8) ull s_mbar[2 * GS];

    const int tid  = threadIdx.x;
    const int wid  = tid >> 5;
    const int lane = tid & 31;
    const int wm   = wid & 3;
    const int wn   = wid >> 2;
    const int bm   = blockIdx.y * 128;
    const int bn   = blockIdx.x * GBN;
    const int z    = blockIdx.z;

    const float* bias = (z == 0) ? bq : (z == 1) ? bk : bv;
    __nv_bfloat16* Ch = (z == 0) ? Qh : (z == 1) ? Kh : Vh;
    __nv_bfloat16* Cl = (z == 0) ? Ql : (z == 1) ? Kl : Vl;

    const uint32_t tile0 = (smem_u32(dsm) + 1023u) & ~1023u;
    const uint32_t mb    = smem_u32(s_mbar);
    const uint32_t full0 = mb;
    const uint32_t emt0  = mb + 8 * GS;

    if (tid == 0) {
        for (int s = 0; s < GS; s++) {
            MBARRIER_INIT(full0 + 8 * s, 1);
            MBARRIER_INIT(emt0 + 8 * s, 8);
        }
    }
    __syncthreads();

    float acc[2][4][4];
#pragma unroll
    for (int i = 0; i < 2; i++)
#pragma unroll
        for (int j = 0; j < 4; j++)
#pragma unroll
            for (int q = 0; q < 4; q++) acc[i][j][q] = 0.0f;

    const int aRow = wm * 32 + (lane & 7) + ((lane >> 3) & 1) * 8;
    const uint32_t aOffBase = (uint32_t)aRow * 128 + ((lane >> 4) & 1) * 16;
    const int bRow = wn * 32 + (lane & 7) + ((lane >> 4) & 1) * 8;
    const uint32_t bOffBase = (uint32_t)bRow * 128 + ((lane >> 3) & 1) * 16;

    gemm_mainloop(&M.aH[z], &M.aL[z], &M.wH[z], &M.wL[z],
                  bm, bn, tile0, full0, emt0, tid, lane, acc, aOffBase, bOffBase);

    const int r0 = bm + wm * 32 + (lane >> 2);
    const int c0 = bn + wn * 32 + (lane & 3) * 2;
#pragma unroll
    for (int sub = 0; sub < 2; sub++) {
#pragma unroll
        for (int nb = 0; nb < 4; nb++) {
            int row = r0 + sub * 16;
            int col = c0 + nb * 8;
            float2 bv2 = *(const float2*)(bias + col);
            float o0x = acc[sub][nb][0] + bv2.x, o0y = acc[sub][nb][1] + bv2.y;
            float o1x = acc[sub][nb][2] + bv2.x, o1y = acc[sub][nb][3] + bv2.y;
            uint32_t h0 = prmt7632(__float_as_uint(o0x), __float_as_uint(o0y));
            uint32_t l0 = cvt_bf16x2(o0y - truncbf(o0y), o0x - truncbf(o0x));
            uint32_t h1 = prmt7632(__float_as_uint(o1x), __float_as_uint(o1y));
            uint32_t l1 = cvt_bf16x2(o1y - truncbf(o1y), o1x - truncbf(o1x));
            *(uint32_t*)(Ch + (size_t)row * GN + col)       = h0;
            *(uint32_t*)(Cl + (size_t)row * GN + col)       = l0;
            *(uint32_t*)(Ch + (size_t)(row + 8) * GN + col) = h1;
            *(uint32_t*)(Cl + (size_t)(row + 8) * GN + col) = l1;
        }
    }
}

// output projection: fp32 epilogue
__global__ __launch_bounds__(256, 2)
void gemm_out(const __grid_constant__ CUtensorMap tmAh,
              const __grid_constant__ CUtensorMap tmAl,
              const __grid_constant__ CUtensorMap tmBh,
              const __grid_constant__ CUtensorMap tmBl,
              const float* __restrict__ bias, float* __restrict__ Cf)
{
    extern __shared__ uint8_t dsm[];
    __shared__ __align__(8) ull s_mbar[2 * GS];

    const int tid  = threadIdx.x;
    const int wid  = tid >> 5;
    const int lane = tid & 31;
    const int wm   = wid & 3;
    const int wn   = wid >> 2;
    const int bm   = blockIdx.y * 128;
    const int bn   = blockIdx.x * GBN;

    const uint32_t tile0 = (smem_u32(dsm) + 1023u) & ~1023u;
    const uint32_t mb    = smem_u32(s_mbar);
    const uint32_t full0 = mb;
    const uint32_t emt0  = mb + 8 * GS;

    if (tid == 0) {
        for (int s = 0; s < GS; s++) {
            MBARRIER_INIT(full0 + 8 * s, 1);
            MBARRIER_INIT(emt0 + 8 * s, 8);
        }
    }
    __syncthreads();

    float acc[2][4][4];
#pragma unroll
    for (int i = 0; i < 2; i++)
#pragma unroll
        for (int j = 0; j < 4; j++)
#pragma unroll
            for (int q = 0; q < 4; q++) acc[i][j][q] = 0.0f;

    const int aRow = wm * 32 + (lane & 7) + ((lane >> 3) & 1) * 8;
    const uint32_t aOffBase = (uint32_t)aRow * 128 + ((lane >> 4) & 1) * 16;
    const int bRow = wn * 32 + (lane & 7) + ((lane >> 4) & 1) * 8;
    const uint32_t bOffBase = (uint32_t)bRow * 128 + ((lane >> 3) & 1) * 16;

    gemm_mainloop(&tmAh, &tmAl, &tmBh, &tmBl,
                  bm, bn, tile0, full0, emt0, tid, lane, acc, aOffBase, bOffBase);

    const int r0 = bm + wm * 32 + (lane >> 2);
    const int c0 = bn + wn * 32 + (lane & 3) * 2;
#pragma unroll
    for (int sub = 0; sub < 2; sub++) {
#pragma unroll
        for (int nb = 0; nb < 4; nb++) {
            int row = r0 + sub * 16;
            int col = c0 + nb * 8;
            float2 bv2 = *(const float2*)(bias + col);
            *(float2*)(Cf + (size_t)row * GN + col) =
                make_float2(acc[sub][nb][0] + bv2.x, acc[sub][nb][1] + bv2.y);
            *(float2*)(Cf + (size_t)(row + 8) * GN + col) =
                make_float2(acc[sub][nb][2] + bv2.x, acc[sub][nb][3] + bv2.y);
        }
    }
}

// ===================================================================
// Causal flash attention via mma.sync, bf16x3 compensated.
// R8: 64-key tiles, 3-stage TMA, 99KB smem -> 2 CTAs/SM.
// CTA: 128 queries x one (b,h). 8 warps x m16 rows.
// ===================================================================
#define FSTG 3
#define FT_B 8192                  // 64 rows x 128B per tensor
#define FST_B (4*FT_B)             // 32768
#define FLASH_SMEM (FSTG*FST_B + 1024)
#define C1F 0.18033688011112042f   // log2(e)/8

__global__ __launch_bounds__(256, 2)
void flash_mma(const __grid_constant__ CUtensorMap tmQh,
               const __grid_constant__ CUtensorMap tmQl,
               const __grid_constant__ CUtensorMap tmKh,
               const __grid_constant__ CUtensorMap tmKl,
               const __grid_constant__ CUtensorMap tmVh,
               const __grid_constant__ CUtensorMap tmVl,
               __nv_bfloat16* __restrict__ Oh, __nv_bfloat16* __restrict__ Ol)
{
    extern __shared__ uint8_t dsm[];
    __shared__ __align__(8) ull s_mbar[2 * FSTG + 1];

    const int tid  = threadIdx.x;
    const int wid  = tid >> 5;
    const int lane = tid & 31;
    const int qt   = (int)gridDim.x - 1 - (int)blockIdx.x;  // heavy CTAs first
    const int h    = blockIdx.y;
    const int b    = blockIdx.z;
    const int q0   = qt * 128;
    const int nkt  = 2 * qt + 2;                             // 64-key tiles
    const int xoff = h * HDIM;
    const int yb   = b * SEQ;

    const uint32_t tile0 = (smem_u32(dsm) + 1023u) & ~1023u;
    const uint32_t mb    = smem_u32(s_mbar);
    const uint32_t full0 = mb;
    const uint32_t emt0  = mb + 8 * FSTG;
    const uint32_t qbar  = mb + 16 * FSTG;

    if (tid == 0) {
        for (int s = 0; s < FSTG; s++) {
            MBARRIER_INIT(full0 + 8 * s, 1);
            MBARRIER_INIT(emt0 + 8 * s, 8);
        }
        MBARRIER_INIT(qbar, 1);
        MBARRIER_EXPECT_TX(qbar, 32768);
        tma2d(tile0,         &tmQh, xoff, yb + q0, qbar);   // 128x64 bf16 = 16KB
        tma2d(tile0 + 16384, &tmQl, xoff, yb + q0, qbar);
    }
    __syncthreads();
    MBARRIER_WAIT_PARITY(qbar, 0);

    // Q fragments (persist in registers)
    const uint32_t aOff = (uint32_t)(wid * 16 + (lane & 7) + ((lane >> 3) & 1) * 8) * 128
                        + ((lane >> 4) & 1) * 16;
    uint32_t qh[4][4], ql[4][4];
#pragma unroll
    for (int kb = 0; kb < 4; kb++) {
        uint32_t off = swz128(aOff + kb * 32);
        LDSM4(qh[kb], tile0 + off);
        LDSM4(ql[kb], tile0 + 16384 + off);
    }
    __syncthreads();   // Q reads done before K/V TMA reuses stage area

    if (tid == 0) {
        int npre = nkt < FSTG ? nkt : FSTG;
        for (int p = 0; p < npre; p++) {
            uint32_t st = tile0 + p * FST_B;
            MBARRIER_EXPECT_TX(full0 + 8 * p, FST_B);
            int y = yb + p * 64;
            tma2d(st,            &tmKh, xoff, y, full0 + 8 * p);
            tma2d(st + FT_B,     &tmKl, xoff, y, full0 + 8 * p);
            tma2d(st + 2 * FT_B, &tmVh, xoff, y, full0 + 8 * p);
            tma2d(st + 3 * FT_B, &tmVl, xoff, y, full0 + 8 * p);
        }
    }

    float m0 = -1e30f, m1 = -1e30f, l0 = 0.0f, l1 = 0.0f;
    float oacc[8][4];
#pragma unroll
    for (int i = 0; i < 8; i++)
#pragma unroll
        for (int j = 0; j < 4; j++) oacc[i][j] = 0.0f;

    const uint32_t kOff = (uint32_t)((lane & 7) + ((lane >> 4) & 1) * 8) * 128
                        + ((lane >> 3) & 1) * 16;
    const uint32_t vOff = (uint32_t)((lane & 7) + ((lane >> 3) & 1) * 8) * 128
                        + ((lane >> 4) & 1) * 16;
    const int qrow = wid * 16 + (lane >> 2);   // local query row (of row pair)

    for (int kt = 0; kt < nkt; kt++) {
        const int s  = kt % FSTG;
        const int ph = (kt / FSTG) & 1;
        MBARRIER_WAIT_PARITY(full0 + 8 * s, ph);
        const uint32_t stb = tile0 + s * FST_B;

        const int tileoff = 64 * kt - q0;        // key offset rel. to q0
        const bool diag  = tileoff >= 0;         // tile intersects causal edge
        const int relW   = wid * 16 + 15 - tileoff;   // warp's max live key col
        const bool skipW = diag && (relW < 0);        // warp fully masked
        int lim2 = relW >> 4; lim2 = lim2 > 3 ? 3 : lim2;  // live 16-key blocks
        int lim1 = relW >> 3; lim1 = lim1 > 7 ? 7 : lim1;  // live 8-key blocks
        const int relT = qrow - tileoff;              // per-thread causal bound

        if (!skipW) {
            float sc[8][4];
#pragma unroll
            for (int i = 0; i < 8; i++)
#pragma unroll
                for (int j = 0; j < 4; j++) sc[i][j] = 0.0f;

            // ---- S = Q K^T: 2 nb2 per group, pass-major over 4 accs ----
#pragma unroll
            for (int kb = 0; kb < 4; kb++) {
#pragma unroll
                for (int g = 0; g < 2; g++) {
                    const int j0 = 2 * g;
                    if (j0 > lim2) break;
                    uint32_t bh[2][4], bl[2][4];
#pragma unroll
                    for (int jj = 0; jj < 2; jj++) {
                        int nb2 = j0 + jj;
                        if (nb2 > lim2) continue;
                        uint32_t off = swz128(kOff + (uint32_t)nb2 * 2048 + (uint32_t)kb * 32);
                        LDSM4(bh[jj], stb + off);
                        LDSM4(bl[jj], stb + FT_B + off);
                    }
#pragma unroll
                    for (int jj = 0; jj < 2; jj++) {   // pass hh
                        int nb2 = j0 + jj;
                        if (nb2 > lim2) continue;
                        MMA16816(sc[2 * nb2],     qh[kb], bh[jj][0], bh[jj][1]);
                        MMA16816(sc[2 * nb2 + 1], qh[kb], bh[jj][2], bh[jj][3]);
                    }
#pragma unroll
                    for (int jj = 0; jj < 2; jj++) {   // pass hl
                        int nb2 = j0 + jj;
                        if (nb2 > lim2) continue;
                        MMA16816(sc[2 * nb2],     qh[kb], bl[jj][0], bl[jj][1]);
                        MMA16816(sc[2 * nb2 + 1], qh[kb], bl[jj][2], bl[jj][3]);
                    }
#pragma unroll
                    for (int jj = 0; jj < 2; jj++) {   // pass lh
                        int nb2 = j0 + jj;
                        if (nb2 > lim2) continue;
                        MMA16816(sc[2 * nb2],     ql[kb], bh[jj][0], bh[jj][1]);
                        MMA16816(sc[2 * nb2 + 1], ql[kb], bh[jj][2], bh[jj][3]);
                    }
                }
            }

            // scale into exp2 domain
#pragma unroll
            for (int nb = 0; nb < 8; nb++) {
                if (nb > lim1) break;
#pragma unroll
                for (int j = 0; j < 4; j++) sc[nb][j] *= C1F;
            }

            // causal mask (diag tiles only)
            if (diag) {
#pragma unroll
                for (int nb = 0; nb < 8; nb++) {
                    if (nb > lim1) break;
                    int c = nb * 8 + (lane & 3) * 2;
                    if (c     > relT)     sc[nb][0] = -1e30f;
                    if (c + 1 > relT)     sc[nb][1] = -1e30f;
                    if (c     > relT + 8) sc[nb][2] = -1e30f;
                    if (c + 1 > relT + 8) sc[nb][3] = -1e30f;
                }
            }

            // ---- online softmax ----
            float mx0 = -1e30f, mx1 = -1e30f;
#pragma unroll
            for (int nb = 0; nb < 8; nb++) {
                if (nb > lim1) break;
                mx0 = fmaxf(mx0, fmaxf(sc[nb][0], sc[nb][1]));
                mx1 = fmaxf(mx1, fmaxf(sc[nb][2], sc[nb][3]));
            }
            mx0 = fmaxf(mx0, __shfl_xor_sync(0xffffffffu, mx0, 1));
            mx0 = fmaxf(mx0, __shfl_xor_sync(0xffffffffu, mx0, 2));
            mx1 = fmaxf(mx1, __shfl_xor_sync(0xffffffffu, mx1, 1));
            mx1 = fmaxf(mx1, __shfl_xor_sync(0xffffffffu, mx1, 2));
            float mn0 = fmaxf(m0, mx0), mn1 = fmaxf(m1, mx1);
            float cor0 = ex2f(m0 - mn0), cor1 = ex2f(m1 - mn1);
            m0 = mn0; m1 = mn1;
            float su0 = 0.0f, su1 = 0.0f;
#pragma unroll
            for (int nb = 0; nb < 8; nb++) {
                if (nb > lim1) break;
                sc[nb][0] = ex2f(sc[nb][0] - mn0); su0 += sc[nb][0];
                sc[nb][1] = ex2f(sc[nb][1] - mn0); su0 += sc[nb][1];
                sc[nb][2] = ex2f(sc[nb][2] - mn1); su1 += sc[nb][2];
                sc[nb][3] = ex2f(sc[nb][3] - mn1); su1 += sc[nb][3];
            }
            su0 += __shfl_xor_sync(0xffffffffu, su0, 1);
            su0 += __shfl_xor_sync(0xffffffffu, su0, 2);
            su1 += __shfl_xor_sync(0xffffffffu, su1, 1);
            su1 += __shfl_xor_sync(0xffffffffu, su1, 2);
            l0 = l0 * cor0 + su0;
            l1 = l1 * cor1 + su1;
#pragma unroll
            for (int nb = 0; nb < 8; nb++) {
                oacc[nb][0] *= cor0; oacc[nb][1] *= cor0;
                oacc[nb][2] *= cor1; oacc[nb][3] *= cor1;
            }

            // ---- O += P V (P in registers) ----
#pragma unroll
            for (int kb2 = 0; kb2 < 4; kb2++) {
                if (kb2 > lim2) break;
                const float* p0 = sc[2 * kb2];
                const float* p1 = sc[2 * kb2 + 1];
                uint32_t aph[4], apl[4];
                aph[0] = prmt7632(__float_as_uint(p0[0]), __float_as_uint(p0[1]));
                aph[1] = prmt7632(__float_as_uint(p0[2]), __float_as_uint(p0[3]));
                aph[2] = prmt7632(__float_as_uint(p1[0]), __float_as_uint(p1[1]));
                aph[3] = prmt7632(__float_as_uint(p1[2]), __float_as_uint(p1[3]));
                apl[0] = cvt_bf16x2(p0[1] - truncbf(p0[1]), p0[0] - truncbf(p0[0]));
                apl[1] = cvt_bf16x2(p0[3] - truncbf(p0[3]), p0[2] - truncbf(p0[2]));
                apl[2] = cvt_bf16x2(p1[1] - truncbf(p1[1]), p1[0] - truncbf(p1[0]));
                apl[3] = cvt_bf16x2(p1[3] - truncbf(p1[3]), p1[2] - truncbf(p1[2]));
#pragma unroll
                for (int h2 = 0; h2 < 2; h2++) {
                    uint32_t vh[2][4], vl[2][4];
#pragma unroll
                    for (int d = 0; d < 2; d++) {
                        int db2 = 2 * h2 + d;
                        uint32_t off = swz128(vOff + (uint32_t)kb2 * 2048 + (uint32_t)db2 * 32);
                        LDSM4T(vh[d], stb + 2 * FT_B + off);
                        LDSM4T(vl[d], stb + 3 * FT_B + off);
                    }
#pragma unroll
                    for (int d = 0; d < 2; d++) {      // pass hh
                        int db2 = 2 * h2 + d;
                        MMA16816(oacc[2 * db2],     aph, vh[d][0], vh[d][1]);
                        MMA16816(oacc[2 * db2 + 1], aph, vh[d][2], vh[d][3]);
                    }
#pragma unroll
                    for (int d = 0; d < 2; d++) {      // pass hl
                        int db2 = 2 * h2 + d;
                        MMA16816(oacc[2 * db2],     aph, vl[d][0], vl[d][1]);
                        MMA16816(oacc[2 * db2 + 1], aph, vl[d][2], vl[d][3]);
                    }
#pragma unroll
                    for (int d = 0; d < 2; d++) {      // pass lh
                        int db2 = 2 * h2 + d;
                        MMA16816(oacc[2 * db2],     apl, vh[d][0], vh[d][1]);
                        MMA16816(oacc[2 * db2 + 1], apl, vh[d][2], vh[d][3]);
                    }
                }
            }
        }

        __syncwarp();
        if (lane == 0) MBARRIER_ARRIVE(emt0 + 8 * s);
        if (kt + FSTG < nkt && tid == 0) {
            MBARRIER_WAIT_PARITY(emt0 + 8 * s, ph);
            MBARRIER_EXPECT_TX(full0 + 8 * s, FST_B);
            int y = yb + (kt + FSTG) * 64;
            tma2d(stb,            &tmKh, xoff, y, full0 + 8 * s);
            tma2d(stb + FT_B,     &tmKl, xoff, y, full0 + 8 * s);
            tma2d(stb + 2 * FT_B, &tmVh, xoff, y, full0 + 8 * s);
            tma2d(stb + 3 * FT_B, &tmVl, xoff, y, full0 + 8 * s);
        }
    }

    // ---- epilogue: normalize, split to bf16 hi/lo, store ----
    float inv0 = 1.0f / l0, inv1 = 1.0f / l1;
    const size_t row0 = (size_t)(yb + q0 + wid * 16 + (lane >> 2));
    const int colb = xoff + (lane & 3) * 2;
#pragma unroll
    for (int nb = 0; nb < 8; nb++) {
        int c = colb + nb * 8;
        float a0 = oacc[nb][0] * inv0, a1 = oacc[nb][1] * inv0;
        float b0 = oacc[nb][2] * inv1, b1 = oacc[nb][3] * inv1;
        uint32_t h0 = prmt7632(__float_as_uint(a0), __float_as_uint(a1));
        uint32_t lo0 = cvt_bf16x2(a1 - truncbf(a1), a0 - truncbf(a0));
        uint32_t h1 = prmt7632(__float_as_uint(b0), __float_as_uint(b1));
        uint32_t lo1 = cvt_bf16x2(b1 - truncbf(b1), b0 - truncbf(b0));
        *(uint32_t*)(Oh + row0 * EMBED + c)       = h0;
        *(uint32_t*)(Ol + row0 * EMBED + c)       = lo0;
        *(uint32_t*)(Oh + (row0 + 8) * EMBED + c) = h1;
        *(uint32_t*)(Ol + (row0 + 8) * EMBED + c) = lo1;
    }
}

// ===================================================================
// host
// ===================================================================
typedef CUresult (*PFN_tmap)(CUtensorMap*, CUtensorMapDataType, cuuint32_t, void*,
                             const cuuint64_t*, const cuuint64_t*, const cuuint32_t*,
                             const cuuint32_t*, CUtensorMapInterleave, CUtensorMapSwizzle,
                             CUtensorMapL2promotion, CUtensorMapFloatOOBfill);

static void make_map2d(PFN_tmap fn, CUtensorMap* m, void* base, int rows, int boxRows) {
    cuuint64_t dims[2]    = {(cuuint64_t)EMBED, (cuuint64_t)rows};
    cuuint64_t strides[1] = {(cuuint64_t)EMBED * 2};
    cuuint32_t box[2]     = {64u, (cuuint32_t)boxRows};
    cuuint32_t estr[2]    = {1u, 1u};
    fn(m, CU_TENSOR_MAP_DATA_TYPE_BFLOAT16, 2, base, dims, strides, box, estr,
       CU_TENSOR_MAP_INTERLEAVE_NONE, CU_TENSOR_MAP_SWIZZLE_128B,
       CU_TENSOR_MAP_L2_PROMOTION_L2_128B, CU_TENSOR_MAP_FLOAT_OOB_FILL_NONE);
}

extern "C" void kernel_launch(void* const* d_in, const int* in_sizes, int n_in,
                              void* d_out, int out_size)
{
    (void)in_sizes; (void)n_in; (void)out_size;
    const float* query = (const float*)d_in[0];
    const float* key   = (const float*)d_in[1];
    const float* value = (const float*)d_in[2];
    // d_in[3]: causal mask — analytically tril, applied in-kernel.
    const float* Wq = (const float*)d_in[4];
    const float* bq = (const float*)d_in[5];
    const float* Wk = (const float*)d_in[6];
    const float* bk = (const float*)d_in[7];
    const float* Wv = (const float*)d_in[8];
    const float* bv = (const float*)d_in[9];
    const float* Wo = (const float*)d_in[10];
    const float* bo = (const float*)d_in[11];
    float* out = (float*)d_out;

    __nv_bfloat16 *pAQh, *pAQl, *pAKh, *pAKl, *pAVh, *pAVl;
    __nv_bfloat16 *pQh, *pQl, *pKh, *pKl, *pVh, *pVl;
    __nv_bfloat16 *pWQh, *pWQl, *pWKh, *pWKl, *pWVh, *pWVl, *pWOh, *pWOl;
    cudaGetSymbolAddress((void**)&pAQh, g_AQh);
    cudaGetSymbolAddress((void**)&pAQl, g_AQl);
    cudaGetSymbolAddress((void**)&pAKh, g_AKh);
    cudaGetSymbolAddress((void**)&pAKl, g_AKl);
    cudaGetSymbolAddress((void**)&pAVh, g_AVh);
    cudaGetSymbolAddress((void**)&pAVl, g_AVl);
    cudaGetSymbolAddress((void**)&pQh, g_Qh);
    cudaGetSymbolAddress((void**)&pQl, g_Ql);
    cudaGetSymbolAddress((void**)&pKh, g_Kh);
    cudaGetSymbolAddress((void**)&pKl, g_Kl);
    cudaGetSymbolAddress((void**)&pVh, g_Vh);
    cudaGetSymbolAddress((void**)&pVl, g_Vl);
    cudaGetSymbolAddress((void**)&pWQh, g_WQh);
    cudaGetSymbolAddress((void**)&pWQl, g_WQl);
    cudaGetSymbolAddress((void**)&pWKh, g_WKh);
    cudaGetSymbolAddress((void**)&pWKl, g_WKl);
    cudaGetSymbolAddress((void**)&pWVh, g_WVh);
    cudaGetSymbolAddress((void**)&pWVl, g_WVl);
    cudaGetSymbolAddress((void**)&pWOh, g_WOh);
    cudaGetSymbolAddress((void**)&pWOl, g_WOl);

    static PFN_tmap pfn = nullptr;
    if (!pfn) {
        cudaDriverEntryPointQueryResult st;
        cudaGetDriverEntryPointByVersion("cuTensorMapEncodeTiled", (void**)&pfn,
                                         12000, cudaEnableDefault, &st);
    }

    QkvMaps qm;
    make_map2d(pfn, &qm.aH[0], pAQh, NTOK, 128);
    make_map2d(pfn, &qm.aL[0], pAQl, NTOK, 128);
    make_map2d(pfn, &qm.aH[1], pAKh, NTOK, 128);
    make_map2d(pfn, &qm.aL[1], pAKl, NTOK, 128);
    make_map2d(pfn, &qm.aH[2], pAVh, NTOK, 128);
    make_map2d(pfn, &qm.aL[2], pAVl, NTOK, 128);
    make_map2d(pfn, &qm.wH[0], pWQh, EMBED, 64);
    make_map2d(pfn, &qm.wL[0], pWQl, EMBED, 64);
    make_map2d(pfn, &qm.wH[1], pWKh, EMBED, 64);
    make_map2d(pfn, &qm.wL[1], pWKl, EMBED, 64);
    make_map2d(pfn, &qm.wH[2], pWVh, EMBED, 64);
    make_map2d(pfn, &qm.wL[2], pWVl, EMBED, 64);

    CUtensorMap mQh, mQl, mKh, mKl, mVh, mVl, mCh, mCl, mWOh, mWOl;
    make_map2d(pfn, &mQh, pQh, NTOK, 128);
    make_map2d(pfn, &mQl, pQl, NTOK, 128);
    make_map2d(pfn, &mKh, pKh, NTOK, 64);    // 64-key boxes for flash K/V
    make_map2d(pfn, &mKl, pKl, NTOK, 64);
    make_map2d(pfn, &mVh, pVh, NTOK, 64);
    make_map2d(pfn, &mVl, pVl, NTOK, 64);
    make_map2d(pfn, &mCh, pAQh, NTOK, 128);  // ctx reuses act-Q buffers
    make_map2d(pfn, &mCl, pAQl, NTOK, 128);
    make_map2d(pfn, &mWOh, pWOh, EMBED, 64);
    make_map2d(pfn, &mWOl, pWOl, EMBED, 64);

    static bool attr_done = false;
    if (!attr_done) {
        cudaFuncSetAttribute(gemm_qkv, cudaFuncAttributeMaxDynamicSharedMemorySize, GEMM_SMEM);
        cudaFuncSetAttribute(gemm_out, cudaFuncAttributeMaxDynamicSharedMemorySize, GEMM_SMEM);
        cudaFuncSetAttribute(flash_mma, cudaFuncAttributeMaxDynamicSharedMemorySize, FLASH_SMEM);
        attr_done = true;
    }

    const int actBlocks = (NTOK * EMBED) / (256 * 4);   // 4096
    const int wBlocks   = (EMBED * EMBED) / (256 * 4);  // 1024

    SplitJobs J;
    J.j[0] = { query, pAQh, pAQl, actBlocks };
    J.j[1] = { key,   pAKh, pAKl, actBlocks };
    J.j[2] = { value, pAVh, pAVl, actBlocks };
    J.j[3] = { Wq,    pWQh, pWQl, wBlocks };
    J.j[4] = { Wk,    pWKh, pWKl, wBlocks };
    J.j[5] = { Wv,    pWVh, pWVl, wBlocks };
    J.j[6] = { Wo,    pWOh, pWOl, wBlocks };

    dim3 gs(actBlocks, 7);
    split_all<<<gs, 256>>>(J);

    dim3 gq(GN / GBN, NTOK / 128, 3);   // (16, 32, 3) = 1536 CTAs
    gemm_qkv<<<gq, 256, GEMM_SMEM>>>(qm, bq, bk, bv, pQh, pQl, pKh, pKl, pVh, pVl);

    dim3 ga(SEQ / 128, HEADS, BSZ);     // (16, 16, 2)
    flash_mma<<<ga, 256, FLASH_SMEM>>>(mQh, mQl, mKh, mKl, mVh, mVl, pAQh, pAQl);

    dim3 go(GN / GBN, NTOK / 128);      // (16, 32) = 512 CTAs
    gemm_out<<<go, 256, GEMM_SMEM>>>(mCh, mCl, mWOh, mWOl, bo, out);
}

// round 9
// speedup vs baseline: 1.1163x; 1.1163x over previous
#include <cuda_runtime.h>
#include <cuda.h>
#include <cuda_bf16.h>
#include <cstdint>

typedef unsigned long long ull;

#define BSZ    2
#define SEQ    2048
#define EMBED  1024
#define HEADS  16
#define HDIM   64
#define NTOK   (BSZ*SEQ)

// ---------------- scratch (no allocations allowed) ----------------
__device__ __nv_bfloat16 g_AQh[NTOK*EMBED];
__device__ __nv_bfloat16 g_AQl[NTOK*EMBED];
__device__ __nv_bfloat16 g_AKh[NTOK*EMBED];
__device__ __nv_bfloat16 g_AKl[NTOK*EMBED];
__device__ __nv_bfloat16 g_AVh[NTOK*EMBED];
__device__ __nv_bfloat16 g_AVl[NTOK*EMBED];
__device__ __nv_bfloat16 g_Qh[NTOK*EMBED];
__device__ __nv_bfloat16 g_Ql[NTOK*EMBED];
__device__ __nv_bfloat16 g_Kh[NTOK*EMBED];
__device__ __nv_bfloat16 g_Kl[NTOK*EMBED];
__device__ __nv_bfloat16 g_Vh[NTOK*EMBED];
__device__ __nv_bfloat16 g_Vl[NTOK*EMBED];
__device__ __nv_bfloat16 g_WQh[EMBED*EMBED];
__device__ __nv_bfloat16 g_WQl[EMBED*EMBED];
__device__ __nv_bfloat16 g_WKh[EMBED*EMBED];
__device__ __nv_bfloat16 g_WKl[EMBED*EMBED];
__device__ __nv_bfloat16 g_WVh[EMBED*EMBED];
__device__ __nv_bfloat16 g_WVl[EMBED*EMBED];
__device__ __nv_bfloat16 g_WOh[EMBED*EMBED];
__device__ __nv_bfloat16 g_WOl[EMBED*EMBED];

// ---------------- PTX helpers (all non-'a' features) ---------------
__device__ __forceinline__ uint32_t smem_u32(const void* p) {
    uint32_t a;
    asm("{ .reg .u64 t; cvta.to.shared.u64 t, %1; cvt.u32.u64 %0, t; }" : "=r"(a) : "l"(p));
    return a;
}

#define MBARRIER_INIT(mbar, cnt) \
    asm volatile("mbarrier.init.shared.b64 [%0], %1;" :: "r"(mbar), "r"(cnt) : "memory")
#define MBARRIER_EXPECT_TX(mbar, bytes) \
    asm volatile("mbarrier.arrive.expect_tx.shared.b64 _, [%0], %1;" :: "r"(mbar), "r"(bytes) : "memory")
#define MBARRIER_ARRIVE(mbar) \
    asm volatile("mbarrier.arrive.release.cta.shared.b64 _, [%0];" :: "r"(mbar) : "memory")

#define MBARRIER_WAIT_PARITY(mbar_addr, phase_parity) do {                                   \
    uint32_t _mbar = (uint32_t)(mbar_addr);                                                  \
    uint32_t _par  = (uint32_t)(phase_parity);                                               \
    uint32_t _done;                                                                          \
    asm volatile("{\n\t.reg .pred p;\n\t"                                                    \
        "mbarrier.try_wait.parity.acquire.cta.shared::cta.b64 p, [%1], %2;\n\t"              \
        "selp.b32 %0, 1, 0, p;\n\t}"                                                         \
        : "=r"(_done) : "r"(_mbar), "r"(_par) : "memory");                                   \
    if (!_done) {                                                                            \
        asm volatile("{\n\t.reg .pred P1;\n\t"                                               \
            "WL_%=:\n\t"                                                                     \
            "mbarrier.try_wait.parity.acquire.cta.shared::cta.b64 P1, [%0], %1, 0x989680;\n\t" \
            "@P1 bra.uni WD_%=;\n\t"                                                         \
            "bra.uni WL_%=;\n\t"                                                             \
            "WD_%=:\n\t}"                                                                    \
            :: "r"(_mbar), "r"(_par) : "memory");                                            \
    }                                                                                        \
} while (0)

__device__ __forceinline__ void tma2d(uint32_t dst, const CUtensorMap* map,
                                      int x, int y, uint32_t mbar) {
    asm volatile(
        "cp.async.bulk.tensor.2d.shared::cta.global.tile.mbarrier::complete_tx::bytes "
        "[%0], [%1, {%2, %3}], [%4];"
        :: "r"(dst), "l"(map), "r"(x), "r"(y), "r"(mbar) : "memory");
}

#define LDSM4(r, addr)                                                           \
    asm volatile("ldmatrix.sync.aligned.m8n8.x4.shared.b16 {%0,%1,%2,%3}, [%4];" \
        : "=r"((r)[0]), "=r"((r)[1]), "=r"((r)[2]), "=r"((r)[3]) : "r"(addr))

#define LDSM4T(r, addr)                                                          \
    asm volatile("ldmatrix.sync.aligned.m8n8.x4.trans.shared.b16 {%0,%1,%2,%3}, [%4];" \
        : "=r"((r)[0]), "=r"((r)[1]), "=r"((r)[2]), "=r"((r)[3]) : "r"(addr))

#define MMA16816(d, a, b0v, b1v)                                                 \
    asm volatile("mma.sync.aligned.m16n8k16.row.col.f32.bf16.bf16.f32 "          \
        "{%0,%1,%2,%3}, {%4,%5,%6,%7}, {%8,%9}, {%0,%1,%2,%3};"                  \
        : "+f"((d)[0]), "+f"((d)[1]), "+f"((d)[2]), "+f"((d)[3])                 \
        : "r"((a)[0]), "r"((a)[1]), "r"((a)[2]), "r"((a)[3]), "r"(b0v), "r"(b1v))

__device__ __forceinline__ uint32_t swz128(uint32_t o) {  // Swizzle<3,4,3>
    return o ^ ((o >> 3) & 0x70u);
}
__device__ __forceinline__ float ex2f(float x) {
    float y; asm("ex2.approx.ftz.f32 %0, %1;" : "=f"(y) : "f"(x)); return y;
}
__device__ __forceinline__ uint32_t prmt7632(uint32_t a, uint32_t b) {
    uint32_t d; asm("prmt.b32 %0, %1, %2, 0x7632;" : "=r"(d) : "r"(a), "r"(b)); return d;
}
__device__ __forceinline__ uint32_t cvt_bf16x2(float hi, float lo) {
    uint32_t d; asm("cvt.rn.bf16x2.f32 %0, %1, %2;" : "=r"(d) : "f"(hi), "f"(lo)); return d;
}
__device__ __forceinline__ float truncbf(float x) {
    return __uint_as_float(__float_as_uint(x) & 0xffff0000u);
}

// ===================================================================
// fused split: 7 tensors, fp32 -> bf16 hi + bf16 lo
// ===================================================================
struct SplitJob { const float* src; __nv_bfloat16* hi; __nv_bfloat16* lo; int nblk; };
struct SplitJobs { SplitJob j[7]; };

__global__ __launch_bounds__(256)
void split_all(const SplitJobs J)
{
    SplitJob jb = J.j[blockIdx.y];
    if ((int)blockIdx.x >= jb.nblk) return;
    int i = (blockIdx.x * 256 + threadIdx.x) * 4;
    float4 v = *(const float4*)(jb.src + i);
    __nv_bfloat16 h0 = __float2bfloat16_rn(v.x);
    __nv_bfloat16 h1 = __float2bfloat16_rn(v.y);
    __nv_bfloat16 h2 = __float2bfloat16_rn(v.z);
    __nv_bfloat16 h3 = __float2bfloat16_rn(v.w);
    __nv_bfloat16 l0 = __float2bfloat16_rn(v.x - __bfloat162float(h0));
    __nv_bfloat16 l1 = __float2bfloat16_rn(v.y - __bfloat162float(h1));
    __nv_bfloat16 l2 = __float2bfloat16_rn(v.z - __bfloat162float(h2));
    __nv_bfloat16 l3 = __float2bfloat16_rn(v.w - __bfloat162float(h3));
    ushort4 hv = make_ushort4(*(unsigned short*)&h0, *(unsigned short*)&h1,
                              *(unsigned short*)&h2, *(unsigned short*)&h3);
    ushort4 lv = make_ushort4(*(unsigned short*)&l0, *(unsigned short*)&l1,
                              *(unsigned short*)&l2, *(unsigned short*)&l3);
    *(ushort4*)(jb.hi + i) = hv;
    *(ushort4*)(jb.lo + i) = lv;
}

// ===================================================================
// GEMM (NT, bf16x3) QKV: 128x64x64 CTA tile, 2-stage TMA, 2 CTAs/SM.
// ===================================================================
#define GK      1024
#define GN      1024
#define GBN     64
#define GBK     64
#define GNK     (GK/GBK)
#define GS      2
#define TILE_A  16384
#define TILE_W  8192
#define STAGE_B (2*TILE_A + 2*TILE_W)   // 49152
#define GEMM_SMEM (GS*STAGE_B + 1024)

struct QkvMaps {
    CUtensorMap aH[3];
    CUtensorMap aL[3];
    CUtensorMap wH[3];
    CUtensorMap wL[3];
};

__device__ __forceinline__ void gemm_mainloop(
    const CUtensorMap* tAh, const CUtensorMap* tAl,
    const CUtensorMap* tBh, const CUtensorMap* tBl,
    int bm, int bn, uint32_t tile0, uint32_t full0, uint32_t emt0,
    int tid, int lane, float acc[2][4][4],
    uint32_t aOffBase, uint32_t bOffBase)
{
    if (tid == 0) {
#pragma unroll
        for (int s = 0; s < GS; s++) {
            uint32_t st = tile0 + s * STAGE_B;
            MBARRIER_EXPECT_TX(full0 + 8 * s, STAGE_B);
            int k0 = s * GBK;
            tma2d(st,                       tAh, k0, bm, full0 + 8 * s);
            tma2d(st + TILE_A,              tAl, k0, bm, full0 + 8 * s);
            tma2d(st + 2 * TILE_A,          tBh, k0, bn, full0 + 8 * s);
            tma2d(st + 2 * TILE_A + TILE_W, tBl, k0, bn, full0 + 8 * s);
        }
    }

    for (int i = 0; i < GNK; i++) {
        const int s  = i % GS;
        const int ph = (i / GS) & 1;
        MBARRIER_WAIT_PARITY(full0 + 8 * s, ph);

        const uint32_t st = tile0 + s * STAGE_B;
        const uint32_t aH = st, aL = st + TILE_A;
        const uint32_t bH = st + 2 * TILE_A, bL = st + 2 * TILE_A + TILE_W;

#pragma unroll
        for (int ks = 0; ks < 4; ks++) {
            const uint32_t kb = (uint32_t)ks * 32;
            uint32_t ah[2][4], al[2][4];
#pragma unroll
            for (int sub = 0; sub < 2; sub++) {
                uint32_t off = swz128(aOffBase + (uint32_t)sub * 16 * 128 + kb);
                LDSM4(ah[sub], aH + off);
                LDSM4(al[sub], aL + off);
            }
            uint32_t bh[2][4], bl[2][4];
#pragma unroll
            for (int nb = 0; nb < 2; nb++) {
                uint32_t off = swz128(bOffBase + (uint32_t)nb * 16 * 128 + kb);
                LDSM4(bh[nb], bH + off);
                LDSM4(bl[nb], bL + off);
            }
            // pass hh
            MMA16816(acc[0][0], ah[0], bh[0][0], bh[0][1]);
            MMA16816(acc[0][1], ah[0], bh[0][2], bh[0][3]);
            MMA16816(acc[0][2], ah[0], bh[1][0], bh[1][1]);
            MMA16816(acc[0][3], ah[0], bh[1][2], bh[1][3]);
            MMA16816(acc[1][0], ah[1], bh[0][0], bh[0][1]);
            MMA16816(acc[1][1], ah[1], bh[0][2], bh[0][3]);
            MMA16816(acc[1][2], ah[1], bh[1][0], bh[1][1]);
            MMA16816(acc[1][3], ah[1], bh[1][2], bh[1][3]);
            // pass hl
            MMA16816(acc[0][0], ah[0], bl[0][0], bl[0][1]);
            MMA16816(acc[0][1], ah[0], bl[0][2], bl[0][3]);
            MMA16816(acc[0][2], ah[0], bl[1][0], bl[1][1]);
            MMA16816(acc[0][3], ah[0], bl[1][2], bl[1][3]);
            MMA16816(acc[1][0], ah[1], bl[0][0], bl[0][1]);
            MMA16816(acc[1][1], ah[1], bl[0][2], bl[0][3]);
            MMA16816(acc[1][2], ah[1], bl[1][0], bl[1][1]);
            MMA16816(acc[1][3], ah[1], bl[1][2], bl[1][3]);
            // pass lh
            MMA16816(acc[0][0], al[0], bh[0][0], bh[0][1]);
            MMA16816(acc[0][1], al[0], bh[0][2], bh[0][3]);
            MMA16816(acc[0][2], al[0], bh[1][0], bh[1][1]);
            MMA16816(acc[0][3], al[0], bh[1][2], bh[1][3]);
            MMA16816(acc[1][0], al[1], bh[0][0], bh[0][1]);
            MMA16816(acc[1][1], al[1], bh[0][2], bh[0][3]);
            MMA16816(acc[1][2], al[1], bh[1][0], bh[1][1]);
            MMA16816(acc[1][3], al[1], bh[1][2], bh[1][3]);
        }
        if (lane == 0) MBARRIER_ARRIVE(emt0 + 8 * s);

        if (i + GS < GNK && tid == 0) {
            MBARRIER_WAIT_PARITY(emt0 + 8 * s, ph);
            MBARRIER_EXPECT_TX(full0 + 8 * s, STAGE_B);
            int k0 = (i + GS) * GBK;
            tma2d(st,                       tAh, k0, bm, full0 + 8 * s);
            tma2d(st + TILE_A,              tAl, k0, bm, full0 + 8 * s);
            tma2d(st + 2 * TILE_A,          tBh, k0, bn, full0 + 8 * s);
            tma2d(st + 2 * TILE_A + TILE_W, tBl, k0, bn, full0 + 8 * s);
        }
    }
}

// fused QKV projection
__global__ __launch_bounds__(256, 2)
void gemm_qkv(const __grid_constant__ QkvMaps M,
              const float* __restrict__ bq, const float* __restrict__ bk,
              const float* __restrict__ bv,
              __nv_bfloat16* __restrict__ Qh, __nv_bfloat16* __restrict__ Ql,
              __nv_bfloat16* __restrict__ Kh, __nv_bfloat16* __restrict__ Kl,
              __nv_bfloat16* __restrict__ Vh, __nv_bfloat16* __restrict__ Vl)
{
    extern __shared__ uint8_t dsm[];
    __shared__ __align__(8) ull s_mbar[2 * GS];

    const int tid  = threadIdx.x;
    const int wid  = tid >> 5;
    const int lane = tid & 31;
    const int wm   = wid & 3;
    const int wn   = wid >> 2;
    const int bm   = blockIdx.y * 128;
    const int bn   = blockIdx.x * GBN;
    const int z    = blockIdx.z;

    const float* bias = (z == 0) ? bq : (z == 1) ? bk : bv;
    __nv_bfloat16* Ch = (z == 0) ? Qh : (z == 1) ? Kh : Vh;
    __nv_bfloat16* Cl = (z == 0) ? Ql : (z == 1) ? Kl : Vl;

    const uint32_t tile0 = (smem_u32(dsm) + 1023u) & ~1023u;
    const uint32_t mb    = smem_u32(s_mbar);
    const uint32_t full0 = mb;
    const uint32_t emt0  = mb + 8 * GS;

    if (tid == 0) {
        for (int s = 0; s < GS; s++) {
            MBARRIER_INIT(full0 + 8 * s, 1);
            MBARRIER_INIT(emt0 + 8 * s, 8);
        }
    }
    __syncthreads();

    float acc[2][4][4];
#pragma unroll
    for (int i = 0; i < 2; i++)
#pragma unroll
        for (int j = 0; j < 4; j++)
#pragma unroll
            for (int q = 0; q < 4; q++) acc[i][j][q] = 0.0f;

    const int aRow = wm * 32 + (lane & 7) + ((lane >> 3) & 1) * 8;
    const uint32_t aOffBase = (uint32_t)aRow * 128 + ((lane >> 4) & 1) * 16;
    const int bRow = wn * 32 + (lane & 7) + ((lane >> 4) & 1) * 8;
    const uint32_t bOffBase = (uint32_t)bRow * 128 + ((lane >> 3) & 1) * 16;

    gemm_mainloop(&M.aH[z], &M.aL[z], &M.wH[z], &M.wL[z],
                  bm, bn, tile0, full0, emt0, tid, lane, acc, aOffBase, bOffBase);

    const int r0 = bm + wm * 32 + (lane >> 2);
    const int c0 = bn + wn * 32 + (lane & 3) * 2;
#pragma unroll
    for (int sub = 0; sub < 2; sub++) {
#pragma unroll
        for (int nb = 0; nb < 4; nb++) {
            int row = r0 + sub * 16;
            int col = c0 + nb * 8;
            float2 bv2 = *(const float2*)(bias + col);
            float o0x = acc[sub][nb][0] + bv2.x, o0y = acc[sub][nb][1] + bv2.y;
            float o1x = acc[sub][nb][2] + bv2.x, o1y = acc[sub][nb][3] + bv2.y;
            uint32_t h0 = prmt7632(__float_as_uint(o0x), __float_as_uint(o0y));
            uint32_t l0 = cvt_bf16x2(o0y - truncbf(o0y), o0x - truncbf(o0x));
            uint32_t h1 = prmt7632(__float_as_uint(o1x), __float_as_uint(o1y));
            uint32_t l1 = cvt_bf16x2(o1y - truncbf(o1y), o1x - truncbf(o1x));
            *(uint32_t*)(Ch + (size_t)row * GN + col)       = h0;
            *(uint32_t*)(Cl + (size_t)row * GN + col)       = l0;
            *(uint32_t*)(Ch + (size_t)(row + 8) * GN + col) = h1;
            *(uint32_t*)(Cl + (size_t)(row + 8) * GN + col) = l1;
        }
    }
}

// ===================================================================
// output projection: 64x64x64 tiles, 3-stage TMA, 2 CTAs/SM,
// 1024 CTAs (3.46 waves -> small tail). fp32 epilogue.
// ===================================================================
#define OS      3
#define OT_A    8192                    // 64 rows x 128B
#define OSTG_B  (2*OT_A + 2*TILE_W)     // 32768
#define OGEMM_SMEM (OS*OSTG_B + 1024)

__global__ __launch_bounds__(256, 2)
void gemm_out(const __grid_constant__ CUtensorMap tmAh,
              const __grid_constant__ CUtensorMap tmAl,
              const __grid_constant__ CUtensorMap tmBh,
              const __grid_constant__ CUtensorMap tmBl,
              const float* __restrict__ bias, float* __restrict__ Cf)
{
    extern __shared__ uint8_t dsm[];
    __shared__ __align__(8) ull s_mbar[2 * OS];

    const int tid  = threadIdx.x;
    const int wid  = tid >> 5;
    const int lane = tid & 31;
    const int wm   = wid & 3;     // 4 m-groups of 16 rows
    const int wn   = wid >> 2;    // 2 n-groups of 32 cols
    const int bm   = blockIdx.y * 64;
    const int bn   = blockIdx.x * GBN;

    const uint32_t tile0 = (smem_u32(dsm) + 1023u) & ~1023u;
    const uint32_t mb    = smem_u32(s_mbar);
    const uint32_t full0 = mb;
    const uint32_t emt0  = mb + 8 * OS;

    if (tid == 0) {
        for (int s = 0; s < OS; s++) {
            MBARRIER_INIT(full0 + 8 * s, 1);
            MBARRIER_INIT(emt0 + 8 * s, 8);
        }
    }
    __syncthreads();

    float acc[4][4];
#pragma unroll
    for (int j = 0; j < 4; j++)
#pragma unroll
        for (int q = 0; q < 4; q++) acc[j][q] = 0.0f;

    const int aRow = wm * 16 + (lane & 7) + ((lane >> 3) & 1) * 8;
    const uint32_t aOffBase = (uint32_t)aRow * 128 + ((lane >> 4) & 1) * 16;
    const int bRow = wn * 32 + (lane & 7) + ((lane >> 4) & 1) * 8;
    const uint32_t bOffBase = (uint32_t)bRow * 128 + ((lane >> 3) & 1) * 16;

    if (tid == 0) {
#pragma unroll
        for (int s = 0; s < OS; s++) {
            uint32_t st = tile0 + s * OSTG_B;
            MBARRIER_EXPECT_TX(full0 + 8 * s, OSTG_B);
            int k0 = s * GBK;
            tma2d(st,                    &tmAh, k0, bm, full0 + 8 * s);
            tma2d(st + OT_A,             &tmAl, k0, bm, full0 + 8 * s);
            tma2d(st + 2 * OT_A,         &tmBh, k0, bn, full0 + 8 * s);
            tma2d(st + 2 * OT_A + TILE_W, &tmBl, k0, bn, full0 + 8 * s);
        }
    }

    for (int i = 0; i < GNK; i++) {
        const int s  = i % OS;
        const int ph = (i / OS) & 1;
        MBARRIER_WAIT_PARITY(full0 + 8 * s, ph);

        const uint32_t st = tile0 + s * OSTG_B;
        const uint32_t aH = st, aL = st + OT_A;
        const uint32_t bH = st + 2 * OT_A, bL = st + 2 * OT_A + TILE_W;

#pragma unroll
        for (int ks = 0; ks < 4; ks++) {
            const uint32_t kb = (uint32_t)ks * 32;
            uint32_t ah[4], al[4];
            {
                uint32_t off = swz128(aOffBase + kb);
                LDSM4(ah, aH + off);
                LDSM4(al, aL + off);
            }
            uint32_t bh[2][4], bl[2][4];
#pragma unroll
            for (int nb = 0; nb < 2; nb++) {
                uint32_t off = swz128(bOffBase + (uint32_t)nb * 16 * 128 + kb);
                LDSM4(bh[nb], bH + off);
                LDSM4(bl[nb], bL + off);
            }
            // pass hh (4 independent accs)
            MMA16816(acc[0], ah, bh[0][0], bh[0][1]);
            MMA16816(acc[1], ah, bh[0][2], bh[0][3]);
            MMA16816(acc[2], ah, bh[1][0], bh[1][1]);
            MMA16816(acc[3], ah, bh[1][2], bh[1][3]);
            // pass hl
            MMA16816(acc[0], ah, bl[0][0], bl[0][1]);
            MMA16816(acc[1], ah, bl[0][2], bl[0][3]);
            MMA16816(acc[2], ah, bl[1][0], bl[1][1]);
            MMA16816(acc[3], ah, bl[1][2], bl[1][3]);
            // pass lh
            MMA16816(acc[0], al, bh[0][0], bh[0][1]);
            MMA16816(acc[1], al, bh[0][2], bh[0][3]);
            MMA16816(acc[2], al, bh[1][0], bh[1][1]);
            MMA16816(acc[3], al, bh[1][2], bh[1][3]);
        }
        if (lane == 0) MBARRIER_ARRIVE(emt0 + 8 * s);

        if (i + OS < GNK && tid == 0) {
            MBARRIER_WAIT_PARITY(emt0 + 8 * s, ph);
            MBARRIER_EXPECT_TX(full0 + 8 * s, OSTG_B);
            int k0 = (i + OS) * GBK;
            tma2d(st,                     &tmAh, k0, bm, full0 + 8 * s);
            tma2d(st + OT_A,              &tmAl, k0, bm, full0 + 8 * s);
            tma2d(st + 2 * OT_A,          &tmBh, k0, bn, full0 + 8 * s);
            tma2d(st + 2 * OT_A + TILE_W, &tmBl, k0, bn, full0 + 8 * s);
        }
    }

    const int r0 = bm + wm * 16 + (lane >> 2);
    const int c0 = bn + wn * 32 + (lane & 3) * 2;
#pragma unroll
    for (int nb = 0; nb < 4; nb++) {
        int col = c0 + nb * 8;
        float2 bv2 = *(const float2*)(bias + col);
        *(float2*)(Cf + (size_t)r0 * GN + col) =
            make_float2(acc[nb][0] + bv2.x, acc[nb][1] + bv2.y);
        *(float2*)(Cf + (size_t)(r0 + 8) * GN + col) =
            make_float2(acc[nb][2] + bv2.x, acc[nb][3] + bv2.y);
    }
}

// ===================================================================
// Causal flash attention via mma.sync, bf16x3 compensated.
// R7 configuration (128-key tiles, 3-stage, 1 CTA/SM) — reverted.
// ===================================================================
#define FSTG 3
#define FT_B 16384
#define FST_B (4*FT_B)
#define FLASH_SMEM (FSTG*FST_B + 1024)
#define C1F 0.18033688011112042f   // log2(e)/8

__global__ __launch_bounds__(256)
void flash_mma(const __grid_constant__ CUtensorMap tmQh,
               const __grid_constant__ CUtensorMap tmQl,
               const __grid_constant__ CUtensorMap tmKh,
               const __grid_constant__ CUtensorMap tmKl,
               const __grid_constant__ CUtensorMap tmVh,
               const __grid_constant__ CUtensorMap tmVl,
               __nv_bfloat16* __restrict__ Oh, __nv_bfloat16* __restrict__ Ol)
{
    extern __shared__ uint8_t dsm[];
    __shared__ __align__(8) ull s_mbar[2 * FSTG + 1];

    const int tid  = threadIdx.x;
    const int wid  = tid >> 5;
    const int lane = tid & 31;
    const int qt   = (int)gridDim.x - 1 - (int)blockIdx.x;
    const int h    = blockIdx.y;
    const int b    = blockIdx.z;
    const int q0   = qt * 128;
    const int nkt  = qt + 1;
    const int xoff = h * HDIM;
    const int yb   = b * SEQ;

    const uint32_t tile0 = (smem_u32(dsm) + 1023u) & ~1023u;
    const uint32_t mb    = smem_u32(s_mbar);
    const uint32_t full0 = mb;
    const uint32_t emt0  = mb + 8 * FSTG;
    const uint32_t qbar  = mb + 16 * FSTG;

    if (tid == 0) {
        for (int s = 0; s < FSTG; s++) {
            MBARRIER_INIT(full0 + 8 * s, 1);
            MBARRIER_INIT(emt0 + 8 * s, 8);
        }
        MBARRIER_INIT(qbar, 1);
        MBARRIER_EXPECT_TX(qbar, 2 * FT_B);
        tma2d(tile0,        &tmQh, xoff, yb + q0, qbar);
        tma2d(tile0 + FT_B, &tmQl, xoff, yb + q0, qbar);
    }
    __syncthreads();
    MBARRIER_WAIT_PARITY(qbar, 0);

    const uint32_t aOff = (uint32_t)(wid * 16 + (lane & 7) + ((lane >> 3) & 1) * 8) * 128
                        + ((lane >> 4) & 1) * 16;
    uint32_t qh[4][4], ql[4][4];
#pragma unroll
    for (int kb = 0; kb < 4; kb++) {
        uint32_t off = swz128(aOff + kb * 32);
        LDSM4(qh[kb], tile0 + off);
        LDSM4(ql[kb], tile0 + FT_B + off);
    }
    __syncthreads();

    if (tid == 0) {
        int npre = nkt < FSTG ? nkt : FSTG;
        for (int p = 0; p < npre; p++) {
            uint32_t st = tile0 + p * FST_B;
            MBARRIER_EXPECT_TX(full0 + 8 * p, FST_B);
            int y = yb + p * 128;
            tma2d(st,            &tmKh, xoff, y, full0 + 8 * p);
            tma2d(st + FT_B,     &tmKl, xoff, y, full0 + 8 * p);
            tma2d(st + 2 * FT_B, &tmVh, xoff, y, full0 + 8 * p);
            tma2d(st + 3 * FT_B, &tmVl, xoff, y, full0 + 8 * p);
        }
    }

    float m0 = -1e30f, m1 = -1e30f, l0 = 0.0f, l1 = 0.0f;
    float oacc[8][4];
#pragma unroll
    for (int i = 0; i < 8; i++)
#pragma unroll
        for (int j = 0; j < 4; j++) oacc[i][j] = 0.0f;

    const uint32_t kOff = (uint32_t)((lane & 7) + ((lane >> 4) & 1) * 8) * 128
                        + ((lane >> 3) & 1) * 16;
    const uint32_t vOff = (uint32_t)((lane & 7) + ((lane >> 3) & 1) * 8) * 128
                        + ((lane >> 4) & 1) * 16;
    const int qrow = wid * 16 + (lane >> 2);
    const int nbLim  = 2 * wid + 1;
    const int nb2Lim = wid;

    for (int kt = 0; kt < nkt; kt++) {
        const int s  = kt % FSTG;
        const int ph = (kt / FSTG) & 1;
        const bool diag = (kt == qt);
        MBARRIER_WAIT_PARITY(full0 + 8 * s, ph);
        const uint32_t stb = tile0 + s * FST_B;

        float sc[16][4];
#pragma unroll
        for (int i = 0; i < 16; i++)
#pragma unroll
            for (int j = 0; j < 4; j++) sc[i][j] = 0.0f;

        // ---- S = Q K^T: groups of 4 k-blocks, pass-major over 8 accs ----
#pragma unroll
        for (int kb = 0; kb < 4; kb++) {
#pragma unroll
            for (int g = 0; g < 2; g++) {
                if (diag && g * 4 > nb2Lim) break;
                uint32_t bh[4][4], bl[4][4];
#pragma unroll
                for (int j = 0; j < 4; j++) {
                    int nb2 = g * 4 + j;
                    if (diag && nb2 > nb2Lim) continue;
                    uint32_t off = swz128(kOff + (uint32_t)nb2 * 2048 + (uint32_t)kb * 32);
                    LDSM4(bh[j], stb + off);
                    LDSM4(bl[j], stb + FT_B + off);
                }
#pragma unroll
                for (int j = 0; j < 4; j++) {       // pass hh
                    int nb2 = g * 4 + j;
                    if (diag && nb2 > nb2Lim) continue;
                    MMA16816(sc[2 * nb2],     qh[kb], bh[j][0], bh[j][1]);
                    MMA16816(sc[2 * nb2 + 1], qh[kb], bh[j][2], bh[j][3]);
                }
#pragma unroll
                for (int j = 0; j < 4; j++) {       // pass hl
                    int nb2 = g * 4 + j;
                    if (diag && nb2 > nb2Lim) continue;
                    MMA16816(sc[2 * nb2],     qh[kb], bl[j][0], bl[j][1]);
                    MMA16816(sc[2 * nb2 + 1], qh[kb], bl[j][2], bl[j][3]);
                }
#pragma unroll
                for (int j = 0; j < 4; j++) {       // pass lh
                    int nb2 = g * 4 + j;
                    if (diag && nb2 > nb2Lim) continue;
                    MMA16816(sc[2 * nb2],     ql[kb], bh[j][0], bh[j][1]);
                    MMA16816(sc[2 * nb2 + 1], ql[kb], bh[j][2], bh[j][3]);
                }
            }
        }

#pragma unroll
        for (int nb = 0; nb < 16; nb++) {
            if (diag && nb > nbLim) break;
#pragma unroll
            for (int j = 0; j < 4; j++) sc[nb][j] *= C1F;
        }

        if (diag) {
#pragma unroll
            for (int nb = 0; nb < 16; nb++) {
                if (nb > nbLim) break;
                int c = nb * 8 + (lane & 3) * 2;
                if (c     > qrow)     sc[nb][0] = -1e30f;
                if (c + 1 > qrow)     sc[nb][1] = -1e30f;
                if (c     > qrow + 8) sc[nb][2] = -1e30f;
                if (c + 1 > qrow + 8) sc[nb][3] = -1e30f;
            }
        }

        float mx0 = -1e30f, mx1 = -1e30f;
#pragma unroll
        for (int nb = 0; nb < 16; nb++) {
            if (diag && nb > nbLim) break;
            mx0 = fmaxf(mx0, fmaxf(sc[nb][0], sc[nb][1]));
            mx1 = fmaxf(mx1, fmaxf(sc[nb][2], sc[nb][3]));
        }
        mx0 = fmaxf(mx0, __shfl_xor_sync(0xffffffffu, mx0, 1));
        mx0 = fmaxf(mx0, __shfl_xor_sync(0xffffffffu, mx0, 2));
        mx1 = fmaxf(mx1, __shfl_xor_sync(0xffffffffu, mx1, 1));
        mx1 = fmaxf(mx1, __shfl_xor_sync(0xffffffffu, mx1, 2));
        float mn0 = fmaxf(m0, mx0), mn1 = fmaxf(m1, mx1);
        float cor0 = ex2f(m0 - mn0), cor1 = ex2f(m1 - mn1);
        m0 = mn0; m1 = mn1;
        float su0 = 0.0f, su1 = 0.0f;
#pragma unroll
        for (int nb = 0; nb < 16; nb++) {
            if (diag && nb > nbLim) break;
            sc[nb][0] = ex2f(sc[nb][0] - mn0); su0 += sc[nb][0];
            sc[nb][1] = ex2f(sc[nb][1] - mn0); su0 += sc[nb][1];
            sc[nb][2] = ex2f(sc[nb][2] - mn1); su1 += sc[nb][2];
            sc[nb][3] = ex2f(sc[nb][3] - mn1); su1 += sc[nb][3];
        }
        su0 += __shfl_xor_sync(0xffffffffu, su0, 1);
        su0 += __shfl_xor_sync(0xffffffffu, su0, 2);
        su1 += __shfl_xor_sync(0xffffffffu, su1, 1);
        su1 += __shfl_xor_sync(0xffffffffu, su1, 2);
        l0 = l0 * cor0 + su0;
        l1 = l1 * cor1 + su1;
#pragma unroll
        for (int nb = 0; nb < 8; nb++) {
            oacc[nb][0] *= cor0; oacc[nb][1] *= cor0;
            oacc[nb][2] *= cor1; oacc[nb][3] *= cor1;
        }

        // ---- O += P V: per kb2, all 4 V-pairs loaded, pass-major over 8 accs ----
#pragma unroll
        for (int kb2 = 0; kb2 < 8; kb2++) {
            if (diag && kb2 > nb2Lim) break;
            const float* p0 = sc[2 * kb2];
            const float* p1 = sc[2 * kb2 + 1];
            uint32_t aph[4], apl[4];
            aph[0] = prmt7632(__float_as_uint(p0[0]), __float_as_uint(p0[1]));
            aph[1] = prmt7632(__float_as_uint(p0[2]), __float_as_uint(p0[3]));
            aph[2] = prmt7632(__float_as_uint(p1[0]), __float_as_uint(p1[1]));
            aph[3] = prmt7632(__float_as_uint(p1[2]), __float_as_uint(p1[3]));
            apl[0] = cvt_bf16x2(p0[1] - truncbf(p0[1]), p0[0] - truncbf(p0[0]));
            apl[1] = cvt_bf16x2(p0[3] - truncbf(p0[3]), p0[2] - truncbf(p0[2]));
            apl[2] = cvt_bf16x2(p1[1] - truncbf(p1[1]), p1[0] - truncbf(p1[0]));
            apl[3] = cvt_bf16x2(p1[3] - truncbf(p1[3]), p1[2] - truncbf(p1[2]));
            uint32_t vh[4][4], vl[4][4];
#pragma unroll
            for (int db2 = 0; db2 < 4; db2++) {
                uint32_t off = swz128(vOff + (uint32_t)kb2 * 2048 + (uint32_t)db2 * 32);
                LDSM4T(vh[db2], stb + 2 * FT_B + off);
                LDSM4T(vl[db2], stb + 3 * FT_B + off);
            }
#pragma unroll
            for (int db2 = 0; db2 < 4; db2++) {     // pass hh
                MMA16816(oacc[2 * db2],     aph, vh[db2][0], vh[db2][1]);
                MMA16816(oacc[2 * db2 + 1], aph, vh[db2][2], vh[db2][3]);
            }
#pragma unroll
            for (int db2 = 0; db2 < 4; db2++) {     // pass hl
                MMA16816(oacc[2 * db2],     aph, vl[db2][0], vl[db2][1]);
                MMA16816(oacc[2 * db2 + 1], aph, vl[db2][2], vl[db2][3]);
            }
#pragma unroll
            for (int db2 = 0; db2 < 4; db2++) {     // pass lh
                MMA16816(oacc[2 * db2],     apl, vh[db2][0], vh[db2][1]);
                MMA16816(oacc[2 * db2 + 1], apl, vh[db2][2], vh[db2][3]);
            }
        }

        __syncwarp();
        if (lane == 0) MBARRIER_ARRIVE(emt0 + 8 * s);
        if (kt + FSTG < nkt && tid == 0) {
            MBARRIER_WAIT_PARITY(emt0 + 8 * s, ph);
            MBARRIER_EXPECT_TX(full0 + 8 * s, FST_B);
            int y = yb + (kt + FSTG) * 128;
            tma2d(stb,            &tmKh, xoff, y, full0 + 8 * s);
            tma2d(stb + FT_B,     &tmKl, xoff, y, full0 + 8 * s);
            tma2d(stb + 2 * FT_B, &tmVh, xoff, y, full0 + 8 * s);
            tma2d(stb + 3 * FT_B, &tmVl, xoff, y, full0 + 8 * s);
        }
    }

    float inv0 = 1.0f / l0, inv1 = 1.0f / l1;
    const size_t row0 = (size_t)(yb + q0 + wid * 16 + (lane >> 2));
    const int colb = xoff + (lane & 3) * 2;
#pragma unroll
    for (int nb = 0; nb < 8; nb++) {
        int c = colb + nb * 8;
        float a0 = oacc[nb][0] * inv0, a1 = oacc[nb][1] * inv0;
        float b0 = oacc[nb][2] * inv1, b1 = oacc[nb][3] * inv1;
        uint32_t h0 = prmt7632(__float_as_uint(a0), __float_as_uint(a1));
        uint32_t lo0 = cvt_bf16x2(a1 - truncbf(a1), a0 - truncbf(a0));
        uint32_t h1 = prmt7632(__float_as_uint(b0), __float_as_uint(b1));
        uint32_t lo1 = cvt_bf16x2(b1 - truncbf(b1), b0 - truncbf(b0));
        *(uint32_t*)(Oh + row0 * EMBED + c)       = h0;
        *(uint32_t*)(Ol + row0 * EMBED + c)       = lo0;
        *(uint32_t*)(Oh + (row0 + 8) * EMBED + c) = h1;
        *(uint32_t*)(Ol + (row0 + 8) * EMBED + c) = lo1;
    }
}

// ===================================================================
// host
// ===================================================================
typedef CUresult (*PFN_tmap)(CUtensorMap*, CUtensorMapDataType, cuuint32_t, void*,
                             const cuuint64_t*, const cuuint64_t*, const cuuint32_t*,
                             const cuuint32_t*, CUtensorMapInterleave, CUtensorMapSwizzle,
                             CUtensorMapL2promotion, CUtensorMapFloatOOBfill);

static void make_map2d(PFN_tmap fn, CUtensorMap* m, void* base, int rows, int boxRows) {
    cuuint64_t dims[2]    = {(cuuint64_t)EMBED, (cuuint64_t)rows};
    cuuint64_t strides[1] = {(cuuint64_t)EMBED * 2};
    cuuint32_t box[2]     = {64u, (cuuint32_t)boxRows};
    cuuint32_t estr[2]    = {1u, 1u};
    fn(m, CU_TENSOR_MAP_DATA_TYPE_BFLOAT16, 2, base, dims, strides, box, estr,
       CU_TENSOR_MAP_INTERLEAVE_NONE, CU_TENSOR_MAP_SWIZZLE_128B,
       CU_TENSOR_MAP_L2_PROMOTION_L2_128B, CU_TENSOR_MAP_FLOAT_OOB_FILL_NONE);
}

extern "C" void kernel_launch(void* const* d_in, const int* in_sizes, int n_in,
                              void* d_out, int out_size)
{
    (void)in_sizes; (void)n_in; (void)out_size;
    const float* query = (const float*)d_in[0];
    const float* key   = (const float*)d_in[1];
    const float* value = (const float*)d_in[2];
    // d_in[3]: causal mask — analytically tril, applied in-kernel.
    const float* Wq = (const float*)d_in[4];
    const float* bq = (const float*)d_in[5];
    const float* Wk = (const float*)d_in[6];
    const float* bk = (const float*)d_in[7];
    const float* Wv = (const float*)d_in[8];
    const float* bv = (const float*)d_in[9];
    const float* Wo = (const float*)d_in[10];
    const float* bo = (const float*)d_in[11];
    float* out = (float*)d_out;

    __nv_bfloat16 *pAQh, *pAQl, *pAKh, *pAKl, *pAVh, *pAVl;
    __nv_bfloat16 *pQh, *pQl, *pKh, *pKl, *pVh, *pVl;
    __nv_bfloat16 *pWQh, *pWQl, *pWKh, *pWKl, *pWVh, *pWVl, *pWOh, *pWOl;
    cudaGetSymbolAddress((void**)&pAQh, g_AQh);
    cudaGetSymbolAddress((void**)&pAQl, g_AQl);
    cudaGetSymbolAddress((void**)&pAKh, g_AKh);
    cudaGetSymbolAddress((void**)&pAKl, g_AKl);
    cudaGetSymbolAddress((void**)&pAVh, g_AVh);
    cudaGetSymbolAddress((void**)&pAVl, g_AVl);
    cudaGetSymbolAddress((void**)&pQh, g_Qh);
    cudaGetSymbolAddress((void**)&pQl, g_Ql);
    cudaGetSymbolAddress((void**)&pKh, g_Kh);
    cudaGetSymbolAddress((void**)&pKl, g_Kl);
    cudaGetSymbolAddress((void**)&pVh, g_Vh);
    cudaGetSymbolAddress((void**)&pVl, g_Vl);
    cudaGetSymbolAddress((void**)&pWQh, g_WQh);
    cudaGetSymbolAddress((void**)&pWQl, g_WQl);
    cudaGetSymbolAddress((void**)&pWKh, g_WKh);
    cudaGetSymbolAddress((void**)&pWKl, g_WKl);
    cudaGetSymbolAddress((void**)&pWVh, g_WVh);
    cudaGetSymbolAddress((void**)&pWVl, g_WVl);
    cudaGetSymbolAddress((void**)&pWOh, g_WOh);
    cudaGetSymbolAddress((void**)&pWOl, g_WOl);

    static PFN_tmap pfn = nullptr;
    if (!pfn) {
        cudaDriverEntryPointQueryResult st;
        cudaGetDriverEntryPointByVersion("cuTensorMapEncodeTiled", (void**)&pfn,
                                         12000, cudaEnableDefault, &st);
    }

    QkvMaps qm;
    make_map2d(pfn, &qm.aH[0], pAQh, NTOK, 128);
    make_map2d(pfn, &qm.aL[0], pAQl, NTOK, 128);
    make_map2d(pfn, &qm.aH[1], pAKh, NTOK, 128);
    make_map2d(pfn, &qm.aL[1], pAKl, NTOK, 128);
    make_map2d(pfn, &qm.aH[2], pAVh, NTOK, 128);
    make_map2d(pfn, &qm.aL[2], pAVl, NTOK, 128);
    make_map2d(pfn, &qm.wH[0], pWQh, EMBED, 64);
    make_map2d(pfn, &qm.wL[0], pWQl, EMBED, 64);
    make_map2d(pfn, &qm.wH[1], pWKh, EMBED, 64);
    make_map2d(pfn, &qm.wL[1], pWKl, EMBED, 64);
    make_map2d(pfn, &qm.wH[2], pWVh, EMBED, 64);
    make_map2d(pfn, &qm.wL[2], pWVl, EMBED, 64);

    CUtensorMap mQh, mQl, mKh, mKl, mVh, mVl, mCh, mCl, mWOh, mWOl;
    make_map2d(pfn, &mQh, pQh, NTOK, 128);
    make_map2d(pfn, &mQl, pQl, NTOK, 128);
    make_map2d(pfn, &mKh, pKh, NTOK, 128);   // flash K/V: 128-key boxes (R7)
    make_map2d(pfn, &mKl, pKl, NTOK, 128);
    make_map2d(pfn, &mVh, pVh, NTOK, 128);
    make_map2d(pfn, &mVl, pVl, NTOK, 128);
    make_map2d(pfn, &mCh, pAQh, NTOK, 64);   // ctx (gemm_out A): 64-row boxes
    make_map2d(pfn, &mCl, pAQl, NTOK, 64);
    make_map2d(pfn, &mWOh, pWOh, EMBED, 64);
    make_map2d(pfn, &mWOl, pWOl, EMBED, 64);

    static bool attr_done = false;
    if (!attr_done) {
        cudaFuncSetAttribute(gemm_qkv, cudaFuncAttributeMaxDynamicSharedMemorySize, GEMM_SMEM);
        cudaFuncSetAttribute(gemm_out, cudaFuncAttributeMaxDynamicSharedMemorySize, OGEMM_SMEM);
        cudaFuncSetAttribute(flash_mma, cudaFuncAttributeMaxDynamicSharedMemorySize, FLASH_SMEM);
        attr_done = true;
    }

    const int actBlocks = (NTOK * EMBED) / (256 * 4);   // 4096
    const int wBlocks   = (EMBED * EMBED) / (256 * 4);  // 1024

    SplitJobs J;
    J.j[0] = { query, pAQh, pAQl, actBlocks };
    J.j[1] = { key,   pAKh, pAKl, actBlocks };
    J.j[2] = { value, pAVh, pAVl, actBlocks };
    J.j[3] = { Wq,    pWQh, pWQl, wBlocks };
    J.j[4] = { Wk,    pWKh, pWKl, wBlocks };
    J.j[5] = { Wv,    pWVh, pWVl, wBlocks };
    J.j[6] = { Wo,    pWOh, pWOl, wBlocks };

    dim3 gs(actBlocks, 7);
    split_all<<<gs, 256>>>(J);

    dim3 gq(GN / GBN, NTOK / 128, 3);   // (16, 32, 3) = 1536 CTAs
    gemm_qkv<<<gq, 256, GEMM_SMEM>>>(qm, bq, bk, bv, pQh, pQl, pKh, pKl, pVh, pVl);

    dim3 ga(SEQ / 128, HEADS, BSZ);     // (16, 16, 2)
    flash_mma<<<ga, 256, FLASH_SMEM>>>(mQh, mQl, mKh, mKl, mVh, mVl, pAQh, pAQl);

    dim3 go(GN / GBN, NTOK / 64);       // (16, 64) = 1024 CTAs
    gemm_out<<<go, 256, OGEMM_SMEM>>>(mCh, mCl, mWOh, mWOl, bo, out);
}

// round 10
// speedup vs baseline: 1.4906x; 1.3353x over previous
#include <cuda_runtime.h>
#include <cuda.h>
#include <cuda_fp16.h>
#include <cstdint>

typedef unsigned long long ull;

#define BSZ    2
#define SEQ    2048
#define EMBED  1024
#define HEADS  16
#define HDIM   64
#define NTOK   (BSZ*SEQ)

// ---------------- scratch (no allocations allowed) ----------------
__device__ __half g_AQh[NTOK*EMBED];   // act-Q hi; later ctx hi
__device__ __half g_AKh[NTOK*EMBED];
__device__ __half g_AVh[NTOK*EMBED];
__device__ __half g_Qh[NTOK*EMBED];
__device__ __half g_Ql[NTOK*EMBED];
__device__ __half g_Kh[NTOK*EMBED];
__device__ __half g_Vh[NTOK*EMBED];
__device__ __half g_WQh[EMBED*EMBED];
__device__ __half g_WQl[EMBED*EMBED];
__device__ __half g_WKh[EMBED*EMBED];
__device__ __half g_WKl[EMBED*EMBED];
__device__ __half g_WVh[EMBED*EMBED];
__device__ __half g_WVl[EMBED*EMBED];
__device__ __half g_WOh[EMBED*EMBED];
__device__ __half g_WOl[EMBED*EMBED];

// ---------------- PTX helpers (all non-'a' features) ---------------
__device__ __forceinline__ uint32_t smem_u32(const void* p) {
    uint32_t a;
    asm("{ .reg .u64 t; cvta.to.shared.u64 t, %1; cvt.u32.u64 %0, t; }" : "=r"(a) : "l"(p));
    return a;
}

#define MBARRIER_INIT(mbar, cnt) \
    asm volatile("mbarrier.init.shared.b64 [%0], %1;" :: "r"(mbar), "r"(cnt) : "memory")
#define MBARRIER_EXPECT_TX(mbar, bytes) \
    asm volatile("mbarrier.arrive.expect_tx.shared.b64 _, [%0], %1;" :: "r"(mbar), "r"(bytes) : "memory")
#define MBARRIER_ARRIVE(mbar) \
    asm volatile("mbarrier.arrive.release.cta.shared.b64 _, [%0];" :: "r"(mbar) : "memory")

#define MBARRIER_WAIT_PARITY(mbar_addr, phase_parity) do {                                   \
    uint32_t _mbar = (uint32_t)(mbar_addr);                                                  \
    uint32_t _par  = (uint32_t)(phase_parity);                                               \
    uint32_t _done;                                                                          \
    asm volatile("{\n\t.reg .pred p;\n\t"                                                    \
        "mbarrier.try_wait.parity.acquire.cta.shared::cta.b64 p, [%1], %2;\n\t"              \
        "selp.b32 %0, 1, 0, p;\n\t}"                                                         \
        : "=r"(_done) : "r"(_mbar), "r"(_par) : "memory");                                   \
    if (!_done) {                                                                            \
        asm volatile("{\n\t.reg .pred P1;\n\t"                                               \
            "WL_%=:\n\t"                                                                     \
            "mbarrier.try_wait.parity.acquire.cta.shared::cta.b64 P1, [%0], %1, 0x989680;\n\t" \
            "@P1 bra.uni WD_%=;\n\t"                                                         \
            "bra.uni WL_%=;\n\t"                                                             \
            "WD_%=:\n\t}"                                                                    \
            :: "r"(_mbar), "r"(_par) : "memory");                                            \
    }                                                                                        \
} while (0)

__device__ __forceinline__ void tma2d(uint32_t dst, const CUtensorMap* map,
                                      int x, int y, uint32_t mbar) {
    asm volatile(
        "cp.async.bulk.tensor.2d.shared::cta.global.tile.mbarrier::complete_tx::bytes "
        "[%0], [%1, {%2, %3}], [%4];"
        :: "r"(dst), "l"(map), "r"(x), "r"(y), "r"(mbar) : "memory");
}

#define LDSM4(r, addr)                                                           \
    asm volatile("ldmatrix.sync.aligned.m8n8.x4.shared.b16 {%0,%1,%2,%3}, [%4];" \
        : "=r"((r)[0]), "=r"((r)[1]), "=r"((r)[2]), "=r"((r)[3]) : "r"(addr))

#define LDSM4T(r, addr)                                                          \
    asm volatile("ldmatrix.sync.aligned.m8n8.x4.trans.shared.b16 {%0,%1,%2,%3}, [%4];" \
        : "=r"((r)[0]), "=r"((r)[1]), "=r"((r)[2]), "=r"((r)[3]) : "r"(addr))

// fp16 MMA, fp32 accumulate
#define MMA16816(d, a, b0v, b1v)                                                 \
    asm volatile("mma.sync.aligned.m16n8k16.row.col.f32.f16.f16.f32 "            \
        "{%0,%1,%2,%3}, {%4,%5,%6,%7}, {%8,%9}, {%0,%1,%2,%3};"                  \
        : "+f"((d)[0]), "+f"((d)[1]), "+f"((d)[2]), "+f"((d)[3])                 \
        : "r"((a)[0]), "r"((a)[1]), "r"((a)[2]), "r"((a)[3]), "r"(b0v), "r"(b1v))

__device__ __forceinline__ uint32_t swz128(uint32_t o) {  // Swizzle<3,4,3>
    return o ^ ((o >> 3) & 0x70u);
}
__device__ __forceinline__ float ex2f(float x) {
    float y; asm("ex2.approx.ftz.f32 %0, %1;" : "=f"(y) : "f"(x)); return y;
}
__device__ __forceinline__ uint32_t h2bits(__half2 h) {
    return *reinterpret_cast<uint32_t*>(&h);
}
// split fp32 pair -> fp16 hi bits + fp16 lo bits (x in low half, y in high)
__device__ __forceinline__ void split_pair(float x, float y, uint32_t &hb, uint32_t &lb) {
    __half2 h = __floats2half2_rn(x, y);
    hb = h2bits(h);
    float2 hf = __half22float2(h);
    __half2 l = __floats2half2_rn(x - hf.x, y - hf.y);
    lb = h2bits(l);
}

// ===================================================================
// fused split: fp32 -> fp16 hi (+ optional lo)
// ===================================================================
struct SplitJob { const float* src; __half* hi; __half* lo; int nblk; };
struct SplitJobs { SplitJob j[7]; };

__global__ __launch_bounds__(256)
void split_all(const SplitJobs J)
{
    SplitJob jb = J.j[blockIdx.y];
    if ((int)blockIdx.x >= jb.nblk) return;
    int i = (blockIdx.x * 256 + threadIdx.x) * 4;
    float4 v = *(const float4*)(jb.src + i);
    __half2 h01 = __floats2half2_rn(v.x, v.y);
    __half2 h23 = __floats2half2_rn(v.z, v.w);
    uint2 hv = make_uint2(h2bits(h01), h2bits(h23));
    *(uint2*)(jb.hi + i) = hv;
    if (jb.lo) {
        float2 f01 = __half22float2(h01);
        float2 f23 = __half22float2(h23);
        __half2 l01 = __floats2half2_rn(v.x - f01.x, v.y - f01.y);
        __half2 l23 = __floats2half2_rn(v.z - f23.x, v.w - f23.y);
        uint2 lv = make_uint2(h2bits(l01), h2bits(l23));
        *(uint2*)(jb.lo + i) = lv;
    }
}

// ===================================================================
// GEMM (NT, fp16x2): C = A(hi) @ (Wh+Wl)^T + bias
// 128x64x64 CTA tile, 3-stage TMA, 2 CTAs/SM.
// Stage = Ah(16K) + Wh(8K) + Wl(8K) = 32KB.
// ===================================================================
#define GK      1024
#define GN      1024
#define GBN     64
#define GBK     64
#define GNK     (GK/GBK)
#define GS      3
#define TILE_A  16384
#define TILE_W  8192
#define STAGE_B (TILE_A + 2*TILE_W)   // 32768
#define GEMM_SMEM (GS*STAGE_B + 1024)

struct QkvMaps {
    CUtensorMap aH[3];
    CUtensorMap wH[3];
    CUtensorMap wL[3];
};

__device__ __forceinline__ void gemm_mainloop(
    const CUtensorMap* tA, const CUtensorMap* tBh, const CUtensorMap* tBl,
    int bm, int bn, uint32_t tile0, uint32_t full0, uint32_t emt0,
    int tid, int lane, float acc[2][4][4],
    uint32_t aOffBase, uint32_t bOffBase)
{
    if (tid == 0) {
#pragma unroll
        for (int s = 0; s < GS; s++) {
            uint32_t st = tile0 + s * STAGE_B;
            MBARRIER_EXPECT_TX(full0 + 8 * s, STAGE_B);
            int k0 = s * GBK;
            tma2d(st,                   tA,  k0, bm, full0 + 8 * s);
            tma2d(st + TILE_A,          tBh, k0, bn, full0 + 8 * s);
            tma2d(st + TILE_A + TILE_W, tBl, k0, bn, full0 + 8 * s);
        }
    }

    for (int i = 0; i < GNK; i++) {
        const int s  = i % GS;
        const int ph = (i / GS) & 1;
        MBARRIER_WAIT_PARITY(full0 + 8 * s, ph);

        const uint32_t st = tile0 + s * STAGE_B;
        const uint32_t aH = st;
        const uint32_t bH = st + TILE_A, bL = st + TILE_A + TILE_W;

#pragma unroll
        for (int ks = 0; ks < 4; ks++) {
            const uint32_t kb = (uint32_t)ks * 32;
            uint32_t ah[2][4];
#pragma unroll
            for (int sub = 0; sub < 2; sub++) {
                uint32_t off = swz128(aOffBase + (uint32_t)sub * 16 * 128 + kb);
                LDSM4(ah[sub], aH + off);
            }
            uint32_t bh[2][4], bl[2][4];
#pragma unroll
            for (int nb = 0; nb < 2; nb++) {
                uint32_t off = swz128(bOffBase + (uint32_t)nb * 16 * 128 + kb);
                LDSM4(bh[nb], bH + off);
                LDSM4(bl[nb], bL + off);
            }
            // pass hh (8 independent accumulators)
            MMA16816(acc[0][0], ah[0], bh[0][0], bh[0][1]);
            MMA16816(acc[0][1], ah[0], bh[0][2], bh[0][3]);
            MMA16816(acc[0][2], ah[0], bh[1][0], bh[1][1]);
            MMA16816(acc[0][3], ah[0], bh[1][2], bh[1][3]);
            MMA16816(acc[1][0], ah[1], bh[0][0], bh[0][1]);
            MMA16816(acc[1][1], ah[1], bh[0][2], bh[0][3]);
            MMA16816(acc[1][2], ah[1], bh[1][0], bh[1][1]);
            MMA16816(acc[1][3], ah[1], bh[1][2], bh[1][3]);
            // pass hl
            MMA16816(acc[0][0], ah[0], bl[0][0], bl[0][1]);
            MMA16816(acc[0][1], ah[0], bl[0][2], bl[0][3]);
            MMA16816(acc[0][2], ah[0], bl[1][0], bl[1][1]);
            MMA16816(acc[0][3], ah[0], bl[1][2], bl[1][3]);
            MMA16816(acc[1][0], ah[1], bl[0][0], bl[0][1]);
            MMA16816(acc[1][1], ah[1], bl[0][2], bl[0][3]);
            MMA16816(acc[1][2], ah[1], bl[1][0], bl[1][1]);
            MMA16816(acc[1][3], ah[1], bl[1][2], bl[1][3]);
        }
        if (lane == 0) MBARRIER_ARRIVE(emt0 + 8 * s);

        if (i + GS < GNK && tid == 0) {
            MBARRIER_WAIT_PARITY(emt0 + 8 * s, ph);
            MBARRIER_EXPECT_TX(full0 + 8 * s, STAGE_B);
            int k0 = (i + GS) * GBK;
            tma2d(st,                   tA,  k0, bm, full0 + 8 * s);
            tma2d(st + TILE_A,          tBh, k0, bn, full0 + 8 * s);
            tma2d(st + TILE_A + TILE_W, tBl, k0, bn, full0 + 8 * s);
        }
    }
}

// fused QKV projection: z=0 -> Q (hi+lo), z=1 -> K (hi), z=2 -> V (hi)
__global__ __launch_bounds__(256, 2)
void gemm_qkv(const __grid_constant__ QkvMaps M,
              const float* __restrict__ bq, const float* __restrict__ bk,
              const float* __restrict__ bv,
              __half* __restrict__ Qh, __half* __restrict__ Ql,
              __half* __restrict__ Kh, __half* __restrict__ Vh)
{
    extern __shared__ uint8_t dsm[];
    __shared__ __align__(8) ull s_mbar[2 * GS];

    const int tid  = threadIdx.x;
    const int wid  = tid >> 5;
    const int lane = tid & 31;
    const int wm   = wid & 3;
    const int wn   = wid >> 2;
    const int bm   = blockIdx.y * 128;
    const int bn   = blockIdx.x * GBN;
    const int z    = blockIdx.z;

    const float* bias = (z == 0) ? bq : (z == 1) ? bk : bv;
    __half* Ch = (z == 0) ? Qh : (z == 1) ? Kh : Vh;
    __half* Cl = (z == 0) ? Ql : nullptr;

    const uint32_t tile0 = (smem_u32(dsm) + 1023u) & ~1023u;
    const uint32_t mb    = smem_u32(s_mbar);
    const uint32_t full0 = mb;
    const uint32_t emt0  = mb + 8 * GS;

    if (tid == 0) {
        for (int s = 0; s < GS; s++) {
            MBARRIER_INIT(full0 + 8 * s, 1);
            MBARRIER_INIT(emt0 + 8 * s, 8);
        }
    }
    __syncthreads();

    float acc[2][4][4];
#pragma unroll
    for (int i = 0; i < 2; i++)
#pragma unroll
        for (int j = 0; j < 4; j++)
#pragma unroll
            for (int q = 0; q < 4; q++) acc[i][j][q] = 0.0f;

    const int aRow = wm * 32 + (lane & 7) + ((lane >> 3) & 1) * 8;
    const uint32_t aOffBase = (uint32_t)aRow * 128 + ((lane >> 4) & 1) * 16;
    const int bRow = wn * 32 + (lane & 7) + ((lane >> 4) & 1) * 8;
    const uint32_t bOffBase = (uint32_t)bRow * 128 + ((lane >> 3) & 1) * 16;

    gemm_mainloop(&M.aH[z], &M.wH[z], &M.wL[z],
                  bm, bn, tile0, full0, emt0, tid, lane, acc, aOffBase, bOffBase);

    const int r0 = bm + wm * 32 + (lane >> 2);
    const int c0 = bn + wn * 32 + (lane & 3) * 2;
#pragma unroll
    for (int sub = 0; sub < 2; sub++) {
#pragma unroll
        for (int nb = 0; nb < 4; nb++) {
            int row = r0 + sub * 16;
            int col = c0 + nb * 8;
            float2 bv2 = *(const float2*)(bias + col);
            float o0x = acc[sub][nb][0] + bv2.x, o0y = acc[sub][nb][1] + bv2.y;
            float o1x = acc[sub][nb][2] + bv2.x, o1y = acc[sub][nb][3] + bv2.y;
            uint32_t h0, l0, h1, l1;
            split_pair(o0x, o0y, h0, l0);
            split_pair(o1x, o1y, h1, l1);
            *(uint32_t*)(Ch + (size_t)row * GN + col)       = h0;
            *(uint32_t*)(Ch + (size_t)(row + 8) * GN + col) = h1;
            if (Cl) {
                *(uint32_t*)(Cl + (size_t)row * GN + col)       = l0;
                *(uint32_t*)(Cl + (size_t)(row + 8) * GN + col) = l1;
            }
        }
    }
}

// output projection: A = ctx hi, B = WOh+WOl; fp32 epilogue
__global__ __launch_bounds__(256, 2)
void gemm_out(const __grid_constant__ CUtensorMap tmA,
              const __grid_constant__ CUtensorMap tmBh,
              const __grid_constant__ CUtensorMap tmBl,
              const float* __restrict__ bias, float* __restrict__ Cf)
{
    extern __shared__ uint8_t dsm[];
    __shared__ __align__(8) ull s_mbar[2 * GS];

    const int tid  = threadIdx.x;
    const int wid  = tid >> 5;
    const int lane = tid & 31;
    const int wm   = wid & 3;
    const int wn   = wid >> 2;
    const int bm   = blockIdx.y * 128;
    const int bn   = blockIdx.x * GBN;

    const uint32_t tile0 = (smem_u32(dsm) + 1023u) & ~1023u;
    const uint32_t mb    = smem_u32(s_mbar);
    const uint32_t full0 = mb;
    const uint32_t emt0  = mb + 8 * GS;

    if (tid == 0) {
        for (int s = 0; s < GS; s++) {
            MBARRIER_INIT(full0 + 8 * s, 1);
            MBARRIER_INIT(emt0 + 8 * s, 8);
        }
    }
    __syncthreads();

    float acc[2][4][4];
#pragma unroll
    for (int i = 0; i < 2; i++)
#pragma unroll
        for (int j = 0; j < 4; j++)
#pragma unroll
            for (int q = 0; q < 4; q++) acc[i][j][q] = 0.0f;

    const int aRow = wm * 32 + (lane & 7) + ((lane >> 3) & 1) * 8;
    const uint32_t aOffBase = (uint32_t)aRow * 128 + ((lane >> 4) & 1) * 16;
    const int bRow = wn * 32 + (lane & 7) + ((lane >> 4) & 1) * 8;
    const uint32_t bOffBase = (uint32_t)bRow * 128 + ((lane >> 3) & 1) * 16;

    gemm_mainloop(&tmA, &tmBh, &tmBl,
                  bm, bn, tile0, full0, emt0, tid, lane, acc, aOffBase, bOffBase);

    const int r0 = bm + wm * 32 + (lane >> 2);
    const int c0 = bn + wn * 32 + (lane & 3) * 2;
#pragma unroll
    for (int sub = 0; sub < 2; sub++) {
#pragma unroll
        for (int nb = 0; nb < 4; nb++) {
            int row = r0 + sub * 16;
            int col = c0 + nb * 8;
            float2 bv2 = *(const float2*)(bias + col);
            *(float2*)(Cf + (size_t)row * GN + col) =
                make_float2(acc[sub][nb][0] + bv2.x, acc[sub][nb][1] + bv2.y);
            *(float2*)(Cf + (size_t)(row + 8) * GN + col) =
                make_float2(acc[sub][nb][2] + bv2.x, acc[sub][nb][3] + bv2.y);
        }
    }
}

// ===================================================================
// Causal flash attention, fp16x2:
//   S = (Qh+Ql)·Kh   (Q hi+lo in registers, K hi-only tile)
//   O = (Ph+Pl)·Vh   (P hi+lo in registers, V hi-only tile)
// 128-key tiles, 3-stage TMA (stage = Kh+Vh = 32KB).
// ===================================================================
#define FSTG 3
#define FT_B 16384                 // one 128x64 fp16 tile
#define FST_B (2*FT_B)             // Kh + Vh
#define FLASH_SMEM (FSTG*FST_B + 1024)
#define C1F 0.18033688011112042f   // log2(e)/8

__global__ __launch_bounds__(256)
void flash_mma(const __grid_constant__ CUtensorMap tmQh,
               const __grid_constant__ CUtensorMap tmQl,
               const __grid_constant__ CUtensorMap tmKh,
               const __grid_constant__ CUtensorMap tmVh,
               __half* __restrict__ Oh)
{
    extern __shared__ uint8_t dsm[];
    __shared__ __align__(8) ull s_mbar[2 * FSTG + 1];

    const int tid  = threadIdx.x;
    const int wid  = tid >> 5;
    const int lane = tid & 31;
    const int qt   = (int)gridDim.x - 1 - (int)blockIdx.x;  // heavy CTAs first
    const int h    = blockIdx.y;
    const int b    = blockIdx.z;
    const int q0   = qt * 128;
    const int nkt  = qt + 1;
    const int xoff = h * HDIM;
    const int yb   = b * SEQ;

    const uint32_t tile0 = (smem_u32(dsm) + 1023u) & ~1023u;
    const uint32_t mb    = smem_u32(s_mbar);
    const uint32_t full0 = mb;
    const uint32_t emt0  = mb + 8 * FSTG;
    const uint32_t qbar  = mb + 16 * FSTG;

    if (tid == 0) {
        for (int s = 0; s < FSTG; s++) {
            MBARRIER_INIT(full0 + 8 * s, 1);
            MBARRIER_INIT(emt0 + 8 * s, 8);
        }
        MBARRIER_INIT(qbar, 1);
        MBARRIER_EXPECT_TX(qbar, 2 * FT_B);
        tma2d(tile0,        &tmQh, xoff, yb + q0, qbar);
        tma2d(tile0 + FT_B, &tmQl, xoff, yb + q0, qbar);
    }
    __syncthreads();
    MBARRIER_WAIT_PARITY(qbar, 0);

    // Q fragments (hi + lo, persist in registers)
    const uint32_t aOff = (uint32_t)(wid * 16 + (lane & 7) + ((lane >> 3) & 1) * 8) * 128
                        + ((lane >> 4) & 1) * 16;
    uint32_t qh[4][4], ql[4][4];
#pragma unroll
    for (int kb = 0; kb < 4; kb++) {
        uint32_t off = swz128(aOff + kb * 32);
        LDSM4(qh[kb], tile0 + off);
        LDSM4(ql[kb], tile0 + FT_B + off);
    }
    __syncthreads();   // Q reads done before K/V TMA reuses stage area

    if (tid == 0) {
        int npre = nkt < FSTG ? nkt : FSTG;
        for (int p = 0; p < npre; p++) {
            uint32_t st = tile0 + p * FST_B;
            MBARRIER_EXPECT_TX(full0 + 8 * p, FST_B);
            int y = yb + p * 128;
            tma2d(st,        &tmKh, xoff, y, full0 + 8 * p);
            tma2d(st + FT_B, &tmVh, xoff, y, full0 + 8 * p);
        }
    }

    float m0 = -1e30f, m1 = -1e30f, l0 = 0.0f, l1 = 0.0f;
    float oacc[8][4];
#pragma unroll
    for (int i = 0; i < 8; i++)
#pragma unroll
        for (int j = 0; j < 4; j++) oacc[i][j] = 0.0f;

    const uint32_t kOff = (uint32_t)((lane & 7) + ((lane >> 4) & 1) * 8) * 128
                        + ((lane >> 3) & 1) * 16;
    const uint32_t vOff = (uint32_t)((lane & 7) + ((lane >> 3) & 1) * 8) * 128
                        + ((lane >> 4) & 1) * 16;
    const int qrow = wid * 16 + (lane >> 2);
    const int nbLim  = 2 * wid + 1;
    const int nb2Lim = wid;

    for (int kt = 0; kt < nkt; kt++) {
        const int s  = kt % FSTG;
        const int ph = (kt / FSTG) & 1;
        const bool diag = (kt == qt);
        MBARRIER_WAIT_PARITY(full0 + 8 * s, ph);
        const uint32_t stb = tile0 + s * FST_B;

        float sc[16][4];
#pragma unroll
        for (int i = 0; i < 16; i++)
#pragma unroll
            for (int j = 0; j < 4; j++) sc[i][j] = 0.0f;

        // ---- S = (Qh+Ql)·Kh : groups of 4 nb2, pass-major over 8 accs ----
#pragma unroll
        for (int kb = 0; kb < 4; kb++) {
#pragma unroll
            for (int g = 0; g < 2; g++) {
                if (diag && g * 4 > nb2Lim) break;
                uint32_t bh[4][4];
#pragma unroll
                for (int j = 0; j < 4; j++) {
                    int nb2 = g * 4 + j;
                    if (diag && nb2 > nb2Lim) continue;
                    uint32_t off = swz128(kOff + (uint32_t)nb2 * 2048 + (uint32_t)kb * 32);
                    LDSM4(bh[j], stb + off);
                }
#pragma unroll
                for (int j = 0; j < 4; j++) {       // pass hh
                    int nb2 = g * 4 + j;
                    if (diag && nb2 > nb2Lim) continue;
                    MMA16816(sc[2 * nb2],     qh[kb], bh[j][0], bh[j][1]);
                    MMA16816(sc[2 * nb2 + 1], qh[kb], bh[j][2], bh[j][3]);
                }
#pragma unroll
                for (int j = 0; j < 4; j++) {       // pass lh
                    int nb2 = g * 4 + j;
                    if (diag && nb2 > nb2Lim) continue;
                    MMA16816(sc[2 * nb2],     ql[kb], bh[j][0], bh[j][1]);
                    MMA16816(sc[2 * nb2 + 1], ql[kb], bh[j][2], bh[j][3]);
                }
            }
        }

#pragma unroll
        for (int nb = 0; nb < 16; nb++) {
            if (diag && nb > nbLim) break;
#pragma unroll
            for (int j = 0; j < 4; j++) sc[nb][j] *= C1F;
        }

        if (diag) {
#pragma unroll
            for (int nb = 0; nb < 16; nb++) {
                if (nb > nbLim) break;
                int c = nb * 8 + (lane & 3) * 2;
                if (c     > qrow)     sc[nb][0] = -1e30f;
                if (c + 1 > qrow)     sc[nb][1] = -1e30f;
                if (c     > qrow + 8) sc[nb][2] = -1e30f;
                if (c + 1 > qrow + 8) sc[nb][3] = -1e30f;
            }
        }

        float mx0 = -1e30f, mx1 = -1e30f;
#pragma unroll
        for (int nb = 0; nb < 16; nb++) {
            if (diag && nb > nbLim) break;
            mx0 = fmaxf(mx0, fmaxf(sc[nb][0], sc[nb][1]));
            mx1 = fmaxf(mx1, fmaxf(sc[nb][2], sc[nb][3]));
        }
        mx0 = fmaxf(mx0, __shfl_xor_sync(0xffffffffu, mx0, 1));
        mx0 = fmaxf(mx0, __shfl_xor_sync(0xffffffffu, mx0, 2));
        mx1 = fmaxf(mx1, __shfl_xor_sync(0xffffffffu, mx1, 1));
        mx1 = fmaxf(mx1, __shfl_xor_sync(0xffffffffu, mx1, 2));
        float mn0 = fmaxf(m0, mx0), mn1 = fmaxf(m1, mx1);
        float cor0 = ex2f(m0 - mn0), cor1 = ex2f(m1 - mn1);
        m0 = mn0; m1 = mn1;
        float su0 = 0.0f, su1 = 0.0f;
#pragma unroll
        for (int nb = 0; nb < 16; nb++) {
            if (diag && nb > nbLim) break;
            sc[nb][0] = ex2f(sc[nb][0] - mn0); su0 += sc[nb][0];
            sc[nb][1] = ex2f(sc[nb][1] - mn0); su0 += sc[nb][1];
            sc[nb][2] = ex2f(sc[nb][2] - mn1); su1 += sc[nb][2];
            sc[nb][3] = ex2f(sc[nb][3] - mn1); su1 += sc[nb][3];
        }
        su0 += __shfl_xor_sync(0xffffffffu, su0, 1);
        su0 += __shfl_xor_sync(0xffffffffu, su0, 2);
        su1 += __shfl_xor_sync(0xffffffffu, su1, 1);
        su1 += __shfl_xor_sync(0xffffffffu, su1, 2);
        l0 = l0 * cor0 + su0;
        l1 = l1 * cor1 + su1;
#pragma unroll
        for (int nb = 0; nb < 8; nb++) {
            oacc[nb][0] *= cor0; oacc[nb][1] *= cor0;
            oacc[nb][2] *= cor1; oacc[nb][3] *= cor1;
        }

        // ---- O += (Ph+Pl)·Vh : per kb2, pass-major over 8 accs ----
#pragma unroll
        for (int kb2 = 0; kb2 < 8; kb2++) {
            if (diag && kb2 > nb2Lim) break;
            const float* p0 = sc[2 * kb2];
            const float* p1 = sc[2 * kb2 + 1];
            uint32_t aph[4], apl[4];
            split_pair(p0[0], p0[1], aph[0], apl[0]);
            split_pair(p0[2], p0[3], aph[1], apl[1]);
            split_pair(p1[0], p1[1], aph[2], apl[2]);
            split_pair(p1[2], p1[3], aph[3], apl[3]);
            uint32_t vh[4][4];
#pragma unroll
            for (int db2 = 0; db2 < 4; db2++) {
                uint32_t off = swz128(vOff + (uint32_t)kb2 * 2048 + (uint32_t)db2 * 32);
                LDSM4T(vh[db2], stb + FT_B + off);
            }
#pragma unroll
            for (int db2 = 0; db2 < 4; db2++) {     // pass h
                MMA16816(oacc[2 * db2],     aph, vh[db2][0], vh[db2][1]);
                MMA16816(oacc[2 * db2 + 1], aph, vh[db2][2], vh[db2][3]);
            }
#pragma unroll
            for (int db2 = 0; db2 < 4; db2++) {     // pass l
                MMA16816(oacc[2 * db2],     apl, vh[db2][0], vh[db2][1]);
                MMA16816(oacc[2 * db2 + 1], apl, vh[db2][2], vh[db2][3]);
            }
        }

        __syncwarp();
        if (lane == 0) MBARRIER_ARRIVE(emt0 + 8 * s);
        if (kt + FSTG < nkt && tid == 0) {
            MBARRIER_WAIT_PARITY(emt0 + 8 * s, ph);
            MBARRIER_EXPECT_TX(full0 + 8 * s, FST_B);
            int y = yb + (kt + FSTG) * 128;
            tma2d(stb,        &tmKh, xoff, y, full0 + 8 * s);
            tma2d(stb + FT_B, &tmVh, xoff, y, full0 + 8 * s);
        }
    }

    // ---- epilogue: normalize, store ctx hi (fp16) ----
    float inv0 = 1.0f / l0, inv1 = 1.0f / l1;
    const size_t row0 = (size_t)(yb + q0 + wid * 16 + (lane >> 2));
    const int colb = xoff + (lane & 3) * 2;
#pragma unroll
    for (int nb = 0; nb < 8; nb++) {
        int c = colb + nb * 8;
        __half2 h0 = __floats2half2_rn(oacc[nb][0] * inv0, oacc[nb][1] * inv0);
        __half2 h1 = __floats2half2_rn(oacc[nb][2] * inv1, oacc[nb][3] * inv1);
        *(uint32_t*)(Oh + row0 * EMBED + c)       = h2bits(h0);
        *(uint32_t*)(Oh + (row0 + 8) * EMBED + c) = h2bits(h1);
    }
}

// ===================================================================
// host
// ===================================================================
typedef CUresult (*PFN_tmap)(CUtensorMap*, CUtensorMapDataType, cuuint32_t, void*,
                             const cuuint64_t*, const cuuint64_t*, const cuuint32_t*,
                             const cuuint32_t*, CUtensorMapInterleave, CUtensorMapSwizzle,
                             CUtensorMapL2promotion, CUtensorMapFloatOOBfill);

static void make_map2d(PFN_tmap fn, CUtensorMap* m, void* base, int rows, int boxRows) {
    cuuint64_t dims[2]    = {(cuuint64_t)EMBED, (cuuint64_t)rows};
    cuuint64_t strides[1] = {(cuuint64_t)EMBED * 2};
    cuuint32_t box[2]     = {64u, (cuuint32_t)boxRows};
    cuuint32_t estr[2]    = {1u, 1u};
    fn(m, CU_TENSOR_MAP_DATA_TYPE_FLOAT16, 2, base, dims, strides, box, estr,
       CU_TENSOR_MAP_INTERLEAVE_NONE, CU_TENSOR_MAP_SWIZZLE_128B,
       CU_TENSOR_MAP_L2_PROMOTION_L2_128B, CU_TENSOR_MAP_FLOAT_OOB_FILL_NONE);
}

extern "C" void kernel_launch(void* const* d_in, const int* in_sizes, int n_in,
                              void* d_out, int out_size)
{
    (void)in_sizes; (void)n_in; (void)out_size;
    const float* query = (const float*)d_in[0];
    const float* key   = (const float*)d_in[1];
    const float* value = (const float*)d_in[2];
    // d_in[3]: causal mask — analytically tril, applied in-kernel.
    const float* Wq = (const float*)d_in[4];
    const float* bq = (const float*)d_in[5];
    const float* Wk = (const float*)d_in[6];
    const float* bk = (const float*)d_in[7];
    const float* Wv = (const float*)d_in[8];
    const float* bv = (const float*)d_in[9];
    const float* Wo = (const float*)d_in[10];
    const float* bo = (const float*)d_in[11];
    float* out = (float*)d_out;

    __half *pAQh, *pAKh, *pAVh, *pQh, *pQl, *pKh, *pVh;
    __half *pWQh, *pWQl, *pWKh, *pWKl, *pWVh, *pWVl, *pWOh, *pWOl;
    cudaGetSymbolAddress((void**)&pAQh, g_AQh);
    cudaGetSymbolAddress((void**)&pAKh, g_AKh);
    cudaGetSymbolAddress((void**)&pAVh, g_AVh);
    cudaGetSymbolAddress((void**)&pQh, g_Qh);
    cudaGetSymbolAddress((void**)&pQl, g_Ql);
    cudaGetSymbolAddress((void**)&pKh, g_Kh);
    cudaGetSymbolAddress((void**)&pVh, g_Vh);
    cudaGetSymbolAddress((void**)&pWQh, g_WQh);
    cudaGetSymbolAddress((void**)&pWQl, g_WQl);
    cudaGetSymbolAddress((void**)&pWKh, g_WKh);
    cudaGetSymbolAddress((void**)&pWKl, g_WKl);
    cudaGetSymbolAddress((void**)&pWVh, g_WVh);
    cudaGetSymbolAddress((void**)&pWVl, g_WVl);
    cudaGetSymbolAddress((void**)&pWOh, g_WOh);
    cudaGetSymbolAddress((void**)&pWOl, g_WOl);

    static PFN_tmap pfn = nullptr;
    if (!pfn) {
        cudaDriverEntryPointQueryResult st;
        cudaGetDriverEntryPointByVersion("cuTensorMapEncodeTiled", (void**)&pfn,
                                         12000, cudaEnableDefault, &st);
    }

    QkvMaps qm;
    make_map2d(pfn, &qm.aH[0], pAQh, NTOK, 128);
    make_map2d(pfn, &qm.aH[1], pAKh, NTOK, 128);
    make_map2d(pfn, &qm.aH[2], pAVh, NTOK, 128);
    make_map2d(pfn, &qm.wH[0], pWQh, EMBED, 64);
    make_map2d(pfn, &qm.wL[0], pWQl, EMBED, 64);
    make_map2d(pfn, &qm.wH[1], pWKh, EMBED, 64);
    make_map2d(pfn, &qm.wL[1], pWKl, EMBED, 64);
    make_map2d(pfn, &qm.wH[2], pWVh, EMBED, 64);
    make_map2d(pfn, &qm.wL[2], pWVl, EMBED, 64);

    CUtensorMap mQh, mQl, mKh, mVh, mCh, mWOh, mWOl;
    make_map2d(pfn, &mQh, pQh, NTOK, 128);
    make_map2d(pfn, &mQl, pQl, NTOK, 128);
    make_map2d(pfn, &mKh, pKh, NTOK, 128);
    make_map2d(pfn, &mVh, pVh, NTOK, 128);
    make_map2d(pfn, &mCh, pAQh, NTOK, 128);   // ctx reuses act-Q hi buffer
    make_map2d(pfn, &mWOh, pWOh, EMBED, 64);
    make_map2d(pfn, &mWOl, pWOl, EMBED, 64);

    static bool attr_done = false;
    if (!attr_done) {
        cudaFuncSetAttribute(gemm_qkv, cudaFuncAttributeMaxDynamicSharedMemorySize, GEMM_SMEM);
        cudaFuncSetAttribute(gemm_out, cudaFuncAttributeMaxDynamicSharedMemorySize, GEMM_SMEM);
        cudaFuncSetAttribute(flash_mma, cudaFuncAttributeMaxDynamicSharedMemorySize, FLASH_SMEM);
        attr_done = true;
    }

    const int actBlocks = (NTOK * EMBED) / (256 * 4);   // 4096
    const int wBlocks   = (EMBED * EMBED) / (256 * 4);  // 1024

    SplitJobs J;
    J.j[0] = { query, pAQh, nullptr, actBlocks };
    J.j[1] = { key,   pAKh, nullptr, actBlocks };
    J.j[2] = { value, pAVh, nullptr, actBlocks };
    J.j[3] = { Wq,    pWQh, pWQl, wBlocks };
    J.j[4] = { Wk,    pWKh, pWKl, wBlocks };
    J.j[5] = { Wv,    pWVh, pWVl, wBlocks };
    J.j[6] = { Wo,    pWOh, pWOl, wBlocks };

    dim3 gs(actBlocks, 7);
    split_all<<<gs, 256>>>(J);

    dim3 gq(GN / GBN, NTOK / 128, 3);   // (16, 32, 3) = 1536 CTAs
    gemm_qkv<<<gq, 256, GEMM_SMEM>>>(qm, bq, bk, bv, pQh, pQl, pKh, pVh);

    dim3 ga(SEQ / 128, HEADS, BSZ);     // (16, 16, 2)
    flash_mma<<<ga, 256, FLASH_SMEM>>>(mQh, mQl, mKh, mVh, pAQh);

    dim3 go(GN / GBN, NTOK / 128);      // (16, 32) = 512 CTAs
    gemm_out<<<go, 256, GEMM_SMEM>>>(mCh, mWOh, mWOl, bo, out);
}

// round 11
// speedup vs baseline: 1.8521x; 1.2425x over previous
#include <cuda_runtime.h>
#include <cuda.h>
#include <cuda_fp16.h>
#include <cstdint>

typedef unsigned long long ull;

#define BSZ    2
#define SEQ    2048
#define EMBED  1024
#define HEADS  16
#define HDIM   64
#define NTOK   (BSZ*SEQ)

// ---------------- scratch (no allocations allowed) ----------------
__device__ __half g_AQh[NTOK*EMBED];   // act-Q hi; later ctx hi
__device__ __half g_AKh[NTOK*EMBED];
__device__ __half g_AVh[NTOK*EMBED];
__device__ __half g_Qh[NTOK*EMBED];
__device__ __half g_Ql[NTOK*EMBED];
__device__ __half g_Kh[NTOK*EMBED];
__device__ __half g_Vh[NTOK*EMBED];
__device__ __half g_WQh[EMBED*EMBED];
__device__ __half g_WKh[EMBED*EMBED];
__device__ __half g_WVh[EMBED*EMBED];
__device__ __half g_WOh[EMBED*EMBED];

// ---------------- PTX helpers (all non-'a' features) ---------------
__device__ __forceinline__ uint32_t smem_u32(const void* p) {
    uint32_t a;
    asm("{ .reg .u64 t; cvta.to.shared.u64 t, %1; cvt.u32.u64 %0, t; }" : "=r"(a) : "l"(p));
    return a;
}

#define MBARRIER_INIT(mbar, cnt) \
    asm volatile("mbarrier.init.shared.b64 [%0], %1;" :: "r"(mbar), "r"(cnt) : "memory")
#define MBARRIER_EXPECT_TX(mbar, bytes) \
    asm volatile("mbarrier.arrive.expect_tx.shared.b64 _, [%0], %1;" :: "r"(mbar), "r"(bytes) : "memory")
#define MBARRIER_ARRIVE(mbar) \
    asm volatile("mbarrier.arrive.release.cta.shared.b64 _, [%0];" :: "r"(mbar) : "memory")

#define MBARRIER_WAIT_PARITY(mbar_addr, phase_parity) do {                                   \
    uint32_t _mbar = (uint32_t)(mbar_addr);                                                  \
    uint32_t _par  = (uint32_t)(phase_parity);                                               \
    uint32_t _done;                                                                          \
    asm volatile("{\n\t.reg .pred p;\n\t"                                                    \
        "mbarrier.try_wait.parity.acquire.cta.shared::cta.b64 p, [%1], %2;\n\t"              \
        "selp.b32 %0, 1, 0, p;\n\t}"                                                         \
        : "=r"(_done) : "r"(_mbar), "r"(_par) : "memory");                                   \
    if (!_done) {                                                                            \
        asm volatile("{\n\t.reg .pred P1;\n\t"                                               \
            "WL_%=:\n\t"                                                                     \
            "mbarrier.try_wait.parity.acquire.cta.shared::cta.b64 P1, [%0], %1, 0x989680;\n\t" \
            "@P1 bra.uni WD_%=;\n\t"                                                         \
            "bra.uni WL_%=;\n\t"                                                             \
            "WD_%=:\n\t}"                                                                    \
            :: "r"(_mbar), "r"(_par) : "memory");                                            \
    }                                                                                        \
} while (0)

__device__ __forceinline__ void tma2d(uint32_t dst, const CUtensorMap* map,
                                      int x, int y, uint32_t mbar) {
    asm volatile(
        "cp.async.bulk.tensor.2d.shared::cta.global.tile.mbarrier::complete_tx::bytes "
        "[%0], [%1, {%2, %3}], [%4];"
        :: "r"(dst), "l"(map), "r"(x), "r"(y), "r"(mbar) : "memory");
}

#define LDSM4(r, addr)                                                           \
    asm volatile("ldmatrix.sync.aligned.m8n8.x4.shared.b16 {%0,%1,%2,%3}, [%4];" \
        : "=r"((r)[0]), "=r"((r)[1]), "=r"((r)[2]), "=r"((r)[3]) : "r"(addr))

#define LDSM4T(r, addr)                                                          \
    asm volatile("ldmatrix.sync.aligned.m8n8.x4.trans.shared.b16 {%0,%1,%2,%3}, [%4];" \
        : "=r"((r)[0]), "=r"((r)[1]), "=r"((r)[2]), "=r"((r)[3]) : "r"(addr))

// fp16 MMA, fp32 accumulate
#define MMA16816(d, a, b0v, b1v)                                                 \
    asm volatile("mma.sync.aligned.m16n8k16.row.col.f32.f16.f16.f32 "            \
        "{%0,%1,%2,%3}, {%4,%5,%6,%7}, {%8,%9}, {%0,%1,%2,%3};"                  \
        : "+f"((d)[0]), "+f"((d)[1]), "+f"((d)[2]), "+f"((d)[3])                 \
        : "r"((a)[0]), "r"((a)[1]), "r"((a)[2]), "r"((a)[3]), "r"(b0v), "r"(b1v))

__device__ __forceinline__ uint32_t swz128(uint32_t o) {  // Swizzle<3,4,3>
    return o ^ ((o >> 3) & 0x70u);
}
__device__ __forceinline__ float ex2f(float x) {
    float y; asm("ex2.approx.ftz.f32 %0, %1;" : "=f"(y) : "f"(x)); return y;
}
__device__ __forceinline__ uint32_t h2bits(__half2 h) {
    return *reinterpret_cast<uint32_t*>(&h);
}
__device__ __forceinline__ void split_pair(float x, float y, uint32_t &hb, uint32_t &lb) {
    __half2 h = __floats2half2_rn(x, y);
    hb = h2bits(h);
    float2 hf = __half22float2(h);
    __half2 l = __floats2half2_rn(x - hf.x, y - hf.y);
    lb = h2bits(l);
}

// ===================================================================
// fused split: fp32 -> fp16 hi (weights + activations, hi-only)
// ===================================================================
struct SplitJob { const float* src; __half* hi; int nblk; };
struct SplitJobs { SplitJob j[7]; };

__global__ __launch_bounds__(256)
void split_all(const SplitJobs J)
{
    SplitJob jb = J.j[blockIdx.y];
    if ((int)blockIdx.x >= jb.nblk) return;
    int i = (blockIdx.x * 256 + threadIdx.x) * 4;
    float4 v = *(const float4*)(jb.src + i);
    __half2 h01 = __floats2half2_rn(v.x, v.y);
    __half2 h23 = __floats2half2_rn(v.z, v.w);
    uint2 hv = make_uint2(h2bits(h01), h2bits(h23));
    *(uint2*)(jb.hi + i) = hv;
}

// ===================================================================
// GEMM (NT, fp16): C = A(hi) @ Wh^T + bias
// 128x64x64 CTA tile, 4-stage TMA, 2 CTAs/SM. Stage = Ah(16K)+Wh(8K).
// ===================================================================
#define GK      1024
#define GN      1024
#define GBN     64
#define GBK     64
#define GNK     (GK/GBK)
#define GS      4
#define TILE_A  16384
#define TILE_W  8192
#define STAGE_B (TILE_A + TILE_W)     // 24576
#define GEMM_SMEM (GS*STAGE_B + 1024) // 99328

struct QkvMaps {
    CUtensorMap aH[3];
    CUtensorMap wH[3];
};

__device__ __forceinline__ void gemm_mainloop(
    const CUtensorMap* tA, const CUtensorMap* tB,
    int bm, int bn, uint32_t tile0, uint32_t full0, uint32_t emt0,
    int tid, int lane, float acc[2][4][4],
    uint32_t aOffBase, uint32_t bOffBase)
{
    if (tid == 0) {
#pragma unroll
        for (int s = 0; s < GS; s++) {
            uint32_t st = tile0 + s * STAGE_B;
            MBARRIER_EXPECT_TX(full0 + 8 * s, STAGE_B);
            int k0 = s * GBK;
            tma2d(st,          tA, k0, bm, full0 + 8 * s);
            tma2d(st + TILE_A, tB, k0, bn, full0 + 8 * s);
        }
    }

    for (int i = 0; i < GNK; i++) {
        const int s  = i % GS;
        const int ph = (i / GS) & 1;
        MBARRIER_WAIT_PARITY(full0 + 8 * s, ph);

        const uint32_t st = tile0 + s * STAGE_B;
        const uint32_t aH = st;
        const uint32_t bH = st + TILE_A;

#pragma unroll
        for (int ks = 0; ks < 4; ks++) {
            const uint32_t kb = (uint32_t)ks * 32;
            uint32_t ah[2][4];
#pragma unroll
            for (int sub = 0; sub < 2; sub++) {
                uint32_t off = swz128(aOffBase + (uint32_t)sub * 16 * 128 + kb);
                LDSM4(ah[sub], aH + off);
            }
            uint32_t bh[2][4];
#pragma unroll
            for (int nb = 0; nb < 2; nb++) {
                uint32_t off = swz128(bOffBase + (uint32_t)nb * 16 * 128 + kb);
                LDSM4(bh[nb], bH + off);
            }
            // 8 independent accumulators
            MMA16816(acc[0][0], ah[0], bh[0][0], bh[0][1]);
            MMA16816(acc[0][1], ah[0], bh[0][2], bh[0][3]);
            MMA16816(acc[0][2], ah[0], bh[1][0], bh[1][1]);
            MMA16816(acc[0][3], ah[0], bh[1][2], bh[1][3]);
            MMA16816(acc[1][0], ah[1], bh[0][0], bh[0][1]);
            MMA16816(acc[1][1], ah[1], bh[0][2], bh[0][3]);
            MMA16816(acc[1][2], ah[1], bh[1][0], bh[1][1]);
            MMA16816(acc[1][3], ah[1], bh[1][2], bh[1][3]);
        }
        if (lane == 0) MBARRIER_ARRIVE(emt0 + 8 * s);

        if (i + GS < GNK && tid == 0) {
            MBARRIER_WAIT_PARITY(emt0 + 8 * s, ph);
            MBARRIER_EXPECT_TX(full0 + 8 * s, STAGE_B);
            int k0 = (i + GS) * GBK;
            tma2d(st,          tA, k0, bm, full0 + 8 * s);
            tma2d(st + TILE_A, tB, k0, bn, full0 + 8 * s);
        }
    }
}

// fused QKV projection: z=0 -> Q (hi+lo), z=1 -> K (hi), z=2 -> V (hi)
__global__ __launch_bounds__(256, 2)
void gemm_qkv(const __grid_constant__ QkvMaps M,
              const float* __restrict__ bq, const float* __restrict__ bk,
              const float* __restrict__ bv,
              __half* __restrict__ Qh, __half* __restrict__ Ql,
              __half* __restrict__ Kh, __half* __restrict__ Vh)
{
    extern __shared__ uint8_t dsm[];
    __shared__ __align__(8) ull s_mbar[2 * GS];

    const int tid  = threadIdx.x;
    const int wid  = tid >> 5;
    const int lane = tid & 31;
    const int wm   = wid & 3;
    const int wn   = wid >> 2;
    const int bm   = blockIdx.y * 128;
    const int bn   = blockIdx.x * GBN;
    const int z    = blockIdx.z;

    const float* bias = (z == 0) ? bq : (z == 1) ? bk : bv;
    __half* Ch = (z == 0) ? Qh : (z == 1) ? Kh : Vh;
    __half* Cl = (z == 0) ? Ql : nullptr;

    const uint32_t tile0 = (smem_u32(dsm) + 1023u) & ~1023u;
    const uint32_t mb    = smem_u32(s_mbar);
    const uint32_t full0 = mb;
    const uint32_t emt0  = mb + 8 * GS;

    if (tid == 0) {
        for (int s = 0; s < GS; s++) {
            MBARRIER_INIT(full0 + 8 * s, 1);
            MBARRIER_INIT(emt0 + 8 * s, 8);
        }
    }
    __syncthreads();

    float acc[2][4][4];
#pragma unroll
    for (int i = 0; i < 2; i++)
#pragma unroll
        for (int j = 0; j < 4; j++)
#pragma unroll
            for (int q = 0; q < 4; q++) acc[i][j][q] = 0.0f;

    const int aRow = wm * 32 + (lane & 7) + ((lane >> 3) & 1) * 8;
    const uint32_t aOffBase = (uint32_t)aRow * 128 + ((lane >> 4) & 1) * 16;
    const int bRow = wn * 32 + (lane & 7) + ((lane >> 4) & 1) * 8;
    const uint32_t bOffBase = (uint32_t)bRow * 128 + ((lane >> 3) & 1) * 16;

    gemm_mainloop(&M.aH[z], &M.wH[z],
                  bm, bn, tile0, full0, emt0, tid, lane, acc, aOffBase, bOffBase);

    const int r0 = bm + wm * 32 + (lane >> 2);
    const int c0 = bn + wn * 32 + (lane & 3) * 2;
#pragma unroll
    for (int sub = 0; sub < 2; sub++) {
#pragma unroll
        for (int nb = 0; nb < 4; nb++) {
            int row = r0 + sub * 16;
            int col = c0 + nb * 8;
            float2 bv2 = *(const float2*)(bias + col);
            float o0x = acc[sub][nb][0] + bv2.x, o0y = acc[sub][nb][1] + bv2.y;
            float o1x = acc[sub][nb][2] + bv2.x, o1y = acc[sub][nb][3] + bv2.y;
            uint32_t h0, l0, h1, l1;
            split_pair(o0x, o0y, h0, l0);
            split_pair(o1x, o1y, h1, l1);
            *(uint32_t*)(Ch + (size_t)row * GN + col)       = h0;
            *(uint32_t*)(Ch + (size_t)(row + 8) * GN + col) = h1;
            if (Cl) {
                *(uint32_t*)(Cl + (size_t)row * GN + col)       = l0;
                *(uint32_t*)(Cl + (size_t)(row + 8) * GN + col) = l1;
            }
        }
    }
}

// output projection: A = ctx hi, B = WOh; fp32 epilogue
__global__ __launch_bounds__(256, 2)
void gemm_out(const __grid_constant__ CUtensorMap tmA,
              const __grid_constant__ CUtensorMap tmB,
              const float* __restrict__ bias, float* __restrict__ Cf)
{
    extern __shared__ uint8_t dsm[];
    __shared__ __align__(8) ull s_mbar[2 * GS];

    const int tid  = threadIdx.x;
    const int wid  = tid >> 5;
    const int lane = tid & 31;
    const int wm   = wid & 3;
    const int wn   = wid >> 2;
    const int bm   = blockIdx.y * 128;
    const int bn   = blockIdx.x * GBN;

    const uint32_t tile0 = (smem_u32(dsm) + 1023u) & ~1023u;
    const uint32_t mb    = smem_u32(s_mbar);
    const uint32_t full0 = mb;
    const uint32_t emt0  = mb + 8 * GS;

    if (tid == 0) {
        for (int s = 0; s < GS; s++) {
            MBARRIER_INIT(full0 + 8 * s, 1);
            MBARRIER_INIT(emt0 + 8 * s, 8);
        }
    }
    __syncthreads();

    float acc[2][4][4];
#pragma unroll
    for (int i = 0; i < 2; i++)
#pragma unroll
        for (int j = 0; j < 4; j++)
#pragma unroll
            for (int q = 0; q < 4; q++) acc[i][j][q] = 0.0f;

    const int aRow = wm * 32 + (lane & 7) + ((lane >> 3) & 1) * 8;
    const uint32_t aOffBase = (uint32_t)aRow * 128 + ((lane >> 4) & 1) * 16;
    const int bRow = wn * 32 + (lane & 7) + ((lane >> 4) & 1) * 8;
    const uint32_t bOffBase = (uint32_t)bRow * 128 + ((lane >> 3) & 1) * 16;

    gemm_mainloop(&tmA, &tmB,
                  bm, bn, tile0, full0, emt0, tid, lane, acc, aOffBase, bOffBase);

    const int r0 = bm + wm * 32 + (lane >> 2);
    const int c0 = bn + wn * 32 + (lane & 3) * 2;
#pragma unroll
    for (int sub = 0; sub < 2; sub++) {
#pragma unroll
        for (int nb = 0; nb < 4; nb++) {
            int row = r0 + sub * 16;
            int col = c0 + nb * 8;
            float2 bv2 = *(const float2*)(bias + col);
            *(float2*)(Cf + (size_t)row * GN + col) =
                make_float2(acc[sub][nb][0] + bv2.x, acc[sub][nb][1] + bv2.y);
            *(float2*)(Cf + (size_t)(row + 8) * GN + col) =
                make_float2(acc[sub][nb][2] + bv2.x, acc[sub][nb][3] + bv2.y);
        }
    }
}

// ===================================================================
// Causal flash attention, fp16x2 (unchanged from R10):
//   S = (Qh+Ql)·Kh ;  O = (Ph+Pl)·Vh
// 128-key tiles, 3-stage TMA (stage = Kh+Vh = 32KB).
// ===================================================================
#define FSTG 3
#define FT_B 16384
#define FST_B (2*FT_B)
#define FLASH_SMEM (FSTG*FST_B + 1024)
#define C1F 0.18033688011112042f   // log2(e)/8

__global__ __launch_bounds__(256)
void flash_mma(const __grid_constant__ CUtensorMap tmQh,
               const __grid_constant__ CUtensorMap tmQl,
               const __grid_constant__ CUtensorMap tmKh,
               const __grid_constant__ CUtensorMap tmVh,
               __half* __restrict__ Oh)
{
    extern __shared__ uint8_t dsm[];
    __shared__ __align__(8) ull s_mbar[2 * FSTG + 1];

    const int tid  = threadIdx.x;
    const int wid  = tid >> 5;
    const int lane = tid & 31;
    const int qt   = (int)gridDim.x - 1 - (int)blockIdx.x;
    const int h    = blockIdx.y;
    const int b    = blockIdx.z;
    const int q0   = qt * 128;
    const int nkt  = qt + 1;
    const int xoff = h * HDIM;
    const int yb   = b * SEQ;

    const uint32_t tile0 = (smem_u32(dsm) + 1023u) & ~1023u;
    const uint32_t mb    = smem_u32(s_mbar);
    const uint32_t full0 = mb;
    const uint32_t emt0  = mb + 8 * FSTG;
    const uint32_t qbar  = mb + 16 * FSTG;

    if (tid == 0) {
        for (int s = 0; s < FSTG; s++) {
            MBARRIER_INIT(full0 + 8 * s, 1);
            MBARRIER_INIT(emt0 + 8 * s, 8);
        }
        MBARRIER_INIT(qbar, 1);
        MBARRIER_EXPECT_TX(qbar, 2 * FT_B);
        tma2d(tile0,        &tmQh, xoff, yb + q0, qbar);
        tma2d(tile0 + FT_B, &tmQl, xoff, yb + q0, qbar);
    }
    __syncthreads();
    MBARRIER_WAIT_PARITY(qbar, 0);

    const uint32_t aOff = (uint32_t)(wid * 16 + (lane & 7) + ((lane >> 3) & 1) * 8) * 128
                        + ((lane >> 4) & 1) * 16;
    uint32_t qh[4][4], ql[4][4];
#pragma unroll
    for (int kb = 0; kb < 4; kb++) {
        uint32_t off = swz128(aOff + kb * 32);
        LDSM4(qh[kb], tile0 + off);
        LDSM4(ql[kb], tile0 + FT_B + off);
    }
    __syncthreads();

    if (tid == 0) {
        int npre = nkt < FSTG ? nkt : FSTG;
        for (int p = 0; p < npre; p++) {
            uint32_t st = tile0 + p * FST_B;
            MBARRIER_EXPECT_TX(full0 + 8 * p, FST_B);
            int y = yb + p * 128;
            tma2d(st,        &tmKh, xoff, y, full0 + 8 * p);
            tma2d(st + FT_B, &tmVh, xoff, y, full0 + 8 * p);
        }
    }

    float m0 = -1e30f, m1 = -1e30f, l0 = 0.0f, l1 = 0.0f;
    float oacc[8][4];
#pragma unroll
    for (int i = 0; i < 8; i++)
#pragma unroll
        for (int j = 0; j < 4; j++) oacc[i][j] = 0.0f;

    const uint32_t kOff = (uint32_t)((lane & 7) + ((lane >> 4) & 1) * 8) * 128
                        + ((lane >> 3) & 1) * 16;
    const uint32_t vOff = (uint32_t)((lane & 7) + ((lane >> 3) & 1) * 8) * 128
                        + ((lane >> 4) & 1) * 16;
    const int qrow = wid * 16 + (lane >> 2);
    const int nbLim  = 2 * wid + 1;
    const int nb2Lim = wid;

    for (int kt = 0; kt < nkt; kt++) {
        const int s  = kt % FSTG;
        const int ph = (kt / FSTG) & 1;
        const bool diag = (kt == qt);
        MBARRIER_WAIT_PARITY(full0 + 8 * s, ph);
        const uint32_t stb = tile0 + s * FST_B;

        float sc[16][4];
#pragma unroll
        for (int i = 0; i < 16; i++)
#pragma unroll
            for (int j = 0; j < 4; j++) sc[i][j] = 0.0f;

#pragma unroll
        for (int kb = 0; kb < 4; kb++) {
#pragma unroll
            for (int g = 0; g < 2; g++) {
                if (diag && g * 4 > nb2Lim) break;
                uint32_t bh[4][4];
#pragma unroll
                for (int j = 0; j < 4; j++) {
                    int nb2 = g * 4 + j;
                    if (diag && nb2 > nb2Lim) continue;
                    uint32_t off = swz128(kOff + (uint32_t)nb2 * 2048 + (uint32_t)kb * 32);
                    LDSM4(bh[j], stb + off);
                }
#pragma unroll
                for (int j = 0; j < 4; j++) {       // pass hh
                    int nb2 = g * 4 + j;
                    if (diag && nb2 > nb2Lim) continue;
                    MMA16816(sc[2 * nb2],     qh[kb], bh[j][0], bh[j][1]);
                    MMA16816(sc[2 * nb2 + 1], qh[kb], bh[j][2], bh[j][3]);
                }
#pragma unroll
                for (int j = 0; j < 4; j++) {       // pass lh
                    int nb2 = g * 4 + j;
                    if (diag && nb2 > nb2Lim) continue;
                    MMA16816(sc[2 * nb2],     ql[kb], bh[j][0], bh[j][1]);
                    MMA16816(sc[2 * nb2 + 1], ql[kb], bh[j][2], bh[j][3]);
                }
            }
        }

#pragma unroll
        for (int nb = 0; nb < 16; nb++) {
            if (diag && nb > nbLim) break;
#pragma unroll
            for (int j = 0; j < 4; j++) sc[nb][j] *= C1F;
        }

        if (diag) {
#pragma unroll
            for (int nb = 0; nb < 16; nb++) {
                if (nb > nbLim) break;
                int c = nb * 8 + (lane & 3) * 2;
                if (c     > qrow)     sc[nb][0] = -1e30f;
                if (c + 1 > qrow)     sc[nb][1] = -1e30f;
                if (c     > qrow + 8) sc[nb][2] = -1e30f;
                if (c + 1 > qrow + 8) sc[nb][3] = -1e30f;
            }
        }

        float mx0 = -1e30f, mx1 = -1e30f;
#pragma unroll
        for (int nb = 0; nb < 16; nb++) {
            if (diag && nb > nbLim) break;
            mx0 = fmaxf(mx0, fmaxf(sc[nb][0], sc[nb][1]));
            mx1 = fmaxf(mx1, fmaxf(sc[nb][2], sc[nb][3]));
        }
        mx0 = fmaxf(mx0, __shfl_xor_sync(0xffffffffu, mx0, 1));
        mx0 = fmaxf(mx0, __shfl_xor_sync(0xffffffffu, mx0, 2));
        mx1 = fmaxf(mx1, __shfl_xor_sync(0xffffffffu, mx1, 1));
        mx1 = fmaxf(mx1, __shfl_xor_sync(0xffffffffu, mx1, 2));
        float mn0 = fmaxf(m0, mx0), mn1 = fmaxf(m1, mx1);
        float cor0 = ex2f(m0 - mn0), cor1 = ex2f(m1 - mn1);
        m0 = mn0; m1 = mn1;
        float su0 = 0.0f, su1 = 0.0f;
#pragma unroll
        for (int nb = 0; nb < 16; nb++) {
            if (diag && nb > nbLim) break;
            sc[nb][0] = ex2f(sc[nb][0] - mn0); su0 += sc[nb][0];
            sc[nb][1] = ex2f(sc[nb][1] - mn0); su0 += sc[nb][1];
            sc[nb][2] = ex2f(sc[nb][2] - mn1); su1 += sc[nb][2];
            sc[nb][3] = ex2f(sc[nb][3] - mn1); su1 += sc[nb][3];
        }
        su0 += __shfl_xor_sync(0xffffffffu, su0, 1);
        su0 += __shfl_xor_sync(0xffffffffu, su0, 2);
        su1 += __shfl_xor_sync(0xffffffffu, su1, 1);
        su1 += __shfl_xor_sync(0xffffffffu, su1, 2);
        l0 = l0 * cor0 + su0;
        l1 = l1 * cor1 + su1;
#pragma unroll
        for (int nb = 0; nb < 8; nb++) {
            oacc[nb][0] *= cor0; oacc[nb][1] *= cor0;
            oacc[nb][2] *= cor1; oacc[nb][3] *= cor1;
        }

#pragma unroll
        for (int kb2 = 0; kb2 < 8; kb2++) {
            if (diag && kb2 > nb2Lim) break;
            const float* p0 = sc[2 * kb2];
            const float* p1 = sc[2 * kb2 + 1];
            uint32_t aph[4], apl[4];
            split_pair(p0[0], p0[1], aph[0], apl[0]);
            split_pair(p0[2], p0[3], aph[1], apl[1]);
            split_pair(p1[0], p1[1], aph[2], apl[2]);
            split_pair(p1[2], p1[3], aph[3], apl[3]);
            uint32_t vh[4][4];
#pragma unroll
            for (int db2 = 0; db2 < 4; db2++) {
                uint32_t off = swz128(vOff + (uint32_t)kb2 * 2048 + (uint32_t)db2 * 32);
                LDSM4T(vh[db2], stb + FT_B + off);
            }
#pragma unroll
            for (int db2 = 0; db2 < 4; db2++) {     // pass h
                MMA16816(oacc[2 * db2],     aph, vh[db2][0], vh[db2][1]);
                MMA16816(oacc[2 * db2 + 1], aph, vh[db2][2], vh[db2][3]);
            }
#pragma unroll
            for (int db2 = 0; db2 < 4; db2++) {     // pass l
                MMA16816(oacc[2 * db2],     apl, vh[db2][0], vh[db2][1]);
                MMA16816(oacc[2 * db2 + 1], apl, vh[db2][2], vh[db2][3]);
            }
        }

        __syncwarp();
        if (lane == 0) MBARRIER_ARRIVE(emt0 + 8 * s);
        if (kt + FSTG < nkt && tid == 0) {
            MBARRIER_WAIT_PARITY(emt0 + 8 * s, ph);
            MBARRIER_EXPECT_TX(full0 + 8 * s, FST_B);
            int y = yb + (kt + FSTG) * 128;
            tma2d(stb,        &tmKh, xoff, y, full0 + 8 * s);
            tma2d(stb + FT_B, &tmVh, xoff, y, full0 + 8 * s);
        }
    }

    float inv0 = 1.0f / l0, inv1 = 1.0f / l1;
    const size_t row0 = (size_t)(yb + q0 + wid * 16 + (lane >> 2));
    const int colb = xoff + (lane & 3) * 2;
#pragma unroll
    for (int nb = 0; nb < 8; nb++) {
        int c = colb + nb * 8;
        __half2 h0 = __floats2half2_rn(oacc[nb][0] * inv0, oacc[nb][1] * inv0);
        __half2 h1 = __floats2half2_rn(oacc[nb][2] * inv1, oacc[nb][3] * inv1);
        *(uint32_t*)(Oh + row0 * EMBED + c)       = h2bits(h0);
        *(uint32_t*)(Oh + (row0 + 8) * EMBED + c) = h2bits(h1);
    }
}

// ===================================================================
// host
// ===================================================================
typedef CUresult (*PFN_tmap)(CUtensorMap*, CUtensorMapDataType, cuuint32_t, void*,
                             const cuuint64_t*, const cuuint64_t*, const cuuint32_t*,
                             const cuuint32_t*, CUtensorMapInterleave, CUtensorMapSwizzle,
                             CUtensorMapL2promotion, CUtensorMapFloatOOBfill);

static void make_map2d(PFN_tmap fn, CUtensorMap* m, void* base, int rows, int boxRows) {
    cuuint64_t dims[2]    = {(cuuint64_t)EMBED, (cuuint64_t)rows};
    cuuint64_t strides[1] = {(cuuint64_t)EMBED * 2};
    cuuint32_t box[2]     = {64u, (cuuint32_t)boxRows};
    cuuint32_t estr[2]    = {1u, 1u};
    fn(m, CU_TENSOR_MAP_DATA_TYPE_FLOAT16, 2, base, dims, strides, box, estr,
       CU_TENSOR_MAP_INTERLEAVE_NONE, CU_TENSOR_MAP_SWIZZLE_128B,
       CU_TENSOR_MAP_L2_PROMOTION_L2_128B, CU_TENSOR_MAP_FLOAT_OOB_FILL_NONE);
}

extern "C" void kernel_launch(void* const* d_in, const int* in_sizes, int n_in,
                              void* d_out, int out_size)
{
    (void)in_sizes; (void)n_in; (void)out_size;
    const float* query = (const float*)d_in[0];
    const float* key   = (const float*)d_in[1];
    const float* value = (const float*)d_in[2];
    // d_in[3]: causal mask — analytically tril, applied in-kernel.
    const float* Wq = (const float*)d_in[4];
    const float* bq = (const float*)d_in[5];
    const float* Wk = (const float*)d_in[6];
    const float* bk = (const float*)d_in[7];
    const float* Wv = (const float*)d_in[8];
    const float* bv = (const float*)d_in[9];
    const float* Wo = (const float*)d_in[10];
    const float* bo = (const float*)d_in[11];
    float* out = (float*)d_out;

    __half *pAQh, *pAKh, *pAVh, *pQh, *pQl, *pKh, *pVh;
    __half *pWQh, *pWKh, *pWVh, *pWOh;
    cudaGetSymbolAddress((void**)&pAQh, g_AQh);
    cudaGetSymbolAddress((void**)&pAKh, g_AKh);
    cudaGetSymbolAddress((void**)&pAVh, g_AVh);
    cudaGetSymbolAddress((void**)&pQh, g_Qh);
    cudaGetSymbolAddress((void**)&pQl, g_Ql);
    cudaGetSymbolAddress((void**)&pKh, g_Kh);
    cudaGetSymbolAddress((void**)&pVh, g_Vh);
    cudaGetSymbolAddress((void**)&pWQh, g_WQh);
    cudaGetSymbolAddress((void**)&pWKh, g_WKh);
    cudaGetSymbolAddress((void**)&pWVh, g_WVh);
    cudaGetSymbolAddress((void**)&pWOh, g_WOh);

    static PFN_tmap pfn = nullptr;
    if (!pfn) {
        cudaDriverEntryPointQueryResult st;
        cudaGetDriverEntryPointByVersion("cuTensorMapEncodeTiled", (void**)&pfn,
                                         12000, cudaEnableDefault, &st);
    }

    QkvMaps qm;
    make_map2d(pfn, &qm.aH[0], pAQh, NTOK, 128);
    make_map2d(pfn, &qm.aH[1], pAKh, NTOK, 128);
    make_map2d(pfn, &qm.aH[2], pAVh, NTOK, 128);
    make_map2d(pfn, &qm.wH[0], pWQh, EMBED, 64);
    make_map2d(pfn, &qm.wH[1], pWKh, EMBED, 64);
    make_map2d(pfn, &qm.wH[2], pWVh, EMBED, 64);

    CUtensorMap mQh, mQl, mKh, mVh, mCh, mWOh;
    make_map2d(pfn, &mQh, pQh, NTOK, 128);
    make_map2d(pfn, &mQl, pQl, NTOK, 128);
    make_map2d(pfn, &mKh, pKh, NTOK, 128);
    make_map2d(pfn, &mVh, pVh, NTOK, 128);
    make_map2d(pfn, &mCh, pAQh, NTOK, 128);   // ctx reuses act-Q hi buffer
    make_map2d(pfn, &mWOh, pWOh, EMBED, 64);

    static bool attr_done = false;
    if (!attr_done) {
        cudaFuncSetAttribute(gemm_qkv, cudaFuncAttributeMaxDynamicSharedMemorySize, GEMM_SMEM);
        cudaFuncSetAttribute(gemm_out, cudaFuncAttributeMaxDynamicSharedMemorySize, GEMM_SMEM);
        cudaFuncSetAttribute(flash_mma, cudaFuncAttributeMaxDynamicSharedMemorySize, FLASH_SMEM);
        attr_done = true;
    }

    const int actBlocks = (NTOK * EMBED) / (256 * 4);   // 4096
    const int wBlocks   = (EMBED * EMBED) / (256 * 4);  // 1024

    SplitJobs J;
    J.j[0] = { query, pAQh, actBlocks };
    J.j[1] = { key,   pAKh, actBlocks };
    J.j[2] = { value, pAVh, actBlocks };
    J.j[3] = { Wq,    pWQh, wBlocks };
    J.j[4] = { Wk,    pWKh, wBlocks };
    J.j[5] = { Wv,    pWVh, wBlocks };
    J.j[6] = { Wo,    pWOh, wBlocks };

    dim3 gs(actBlocks, 7);
    split_all<<<gs, 256>>>(J);

    dim3 gq(GN / GBN, NTOK / 128, 3);   // (16, 32, 3) = 1536 CTAs
    gemm_qkv<<<gq, 256, GEMM_SMEM>>>(qm, bq, bk, bv, pQh, pQl, pKh, pVh);

    dim3 ga(SEQ / 128, HEADS, BSZ);     // (16, 16, 2)
    flash_mma<<<ga, 256, FLASH_SMEM>>>(mQh, mQl, mKh, mVh, pAQh);

    dim3 go(GN / GBN, NTOK / 128);      // (16, 32) = 512 CTAs
    gemm_out<<<go, 256, GEMM_SMEM>>>(mCh, mWOh, bo, out);
}

// round 12
// speedup vs baseline: 2.2161x; 1.1965x over previous
#include <cuda_runtime.h>
#include <cuda.h>
#include <cuda_fp16.h>
#include <cstdint>

typedef unsigned long long ull;

#define BSZ    2
#define SEQ    2048
#define EMBED  1024
#define HEADS  16
#define HDIM   64
#define NTOK   (BSZ*SEQ)

// ---------------- scratch (no allocations allowed) ----------------
__device__ __half g_AQh[NTOK*EMBED];   // act-Q hi; later ctx hi
__device__ __half g_AKh[NTOK*EMBED];
__device__ __half g_AVh[NTOK*EMBED];
__device__ __half g_Qh[NTOK*EMBED];
__device__ __half g_Kh[NTOK*EMBED];
__device__ __half g_Vh[NTOK*EMBED];
__device__ __half g_WQh[EMBED*EMBED];
__device__ __half g_WKh[EMBED*EMBED];
__device__ __half g_WVh[EMBED*EMBED];
__device__ __half g_WOh[EMBED*EMBED];

// ---------------- PTX helpers (all non-'a' features) ---------------
__device__ __forceinline__ uint32_t smem_u32(const void* p) {
    uint32_t a;
    asm("{ .reg .u64 t; cvta.to.shared.u64 t, %1; cvt.u32.u64 %0, t; }" : "=r"(a) : "l"(p));
    return a;
}

#define MBARRIER_INIT(mbar, cnt) \
    asm volatile("mbarrier.init.shared.b64 [%0], %1;" :: "r"(mbar), "r"(cnt) : "memory")
#define MBARRIER_EXPECT_TX(mbar, bytes) \
    asm volatile("mbarrier.arrive.expect_tx.shared.b64 _, [%0], %1;" :: "r"(mbar), "r"(bytes) : "memory")
#define MBARRIER_ARRIVE(mbar) \
    asm volatile("mbarrier.arrive.release.cta.shared.b64 _, [%0];" :: "r"(mbar) : "memory")

#define MBARRIER_WAIT_PARITY(mbar_addr, phase_parity) do {                                   \
    uint32_t _mbar = (uint32_t)(mbar_addr);                                                  \
    uint32_t _par  = (uint32_t)(phase_parity);                                               \
    uint32_t _done;                                                                          \
    asm volatile("{\n\t.reg .pred p;\n\t"                                                    \
        "mbarrier.try_wait.parity.acquire.cta.shared::cta.b64 p, [%1], %2;\n\t"              \
        "selp.b32 %0, 1, 0, p;\n\t}"                                                         \
        : "=r"(_done) : "r"(_mbar), "r"(_par) : "memory");                                   \
    if (!_done) {                                                                            \
        asm volatile("{\n\t.reg .pred P1;\n\t"                                               \
            "WL_%=:\n\t"                                                                     \
            "mbarrier.try_wait.parity.acquire.cta.shared::cta.b64 P1, [%0], %1, 0x989680;\n\t" \
            "@P1 bra.uni WD_%=;\n\t"                                                         \
            "bra.uni WL_%=;\n\t"                                                             \
            "WD_%=:\n\t}"                                                                    \
            :: "r"(_mbar), "r"(_par) : "memory");                                            \
    }                                                                                        \
} while (0)

__device__ __forceinline__ void tma2d(uint32_t dst, const CUtensorMap* map,
                                      int x, int y, uint32_t mbar) {
    asm volatile(
        "cp.async.bulk.tensor.2d.shared::cta.global.tile.mbarrier::complete_tx::bytes "
        "[%0], [%1, {%2, %3}], [%4];"
        :: "r"(dst), "l"(map), "r"(x), "r"(y), "r"(mbar) : "memory");
}

#define LDSM4(r, addr)                                                           \
    asm volatile("ldmatrix.sync.aligned.m8n8.x4.shared.b16 {%0,%1,%2,%3}, [%4];" \
        : "=r"((r)[0]), "=r"((r)[1]), "=r"((r)[2]), "=r"((r)[3]) : "r"(addr))

#define LDSM4T(r, addr)                                                          \
    asm volatile("ldmatrix.sync.aligned.m8n8.x4.trans.shared.b16 {%0,%1,%2,%3}, [%4];" \
        : "=r"((r)[0]), "=r"((r)[1]), "=r"((r)[2]), "=r"((r)[3]) : "r"(addr))

// fp16 MMA, fp32 accumulate
#define MMA16816(d, a, b0v, b1v)                                                 \
    asm volatile("mma.sync.aligned.m16n8k16.row.col.f32.f16.f16.f32 "            \
        "{%0,%1,%2,%3}, {%4,%5,%6,%7}, {%8,%9}, {%0,%1,%2,%3};"                  \
        : "+f"((d)[0]), "+f"((d)[1]), "+f"((d)[2]), "+f"((d)[3])                 \
        : "r"((a)[0]), "r"((a)[1]), "r"((a)[2]), "r"((a)[3]), "r"(b0v), "r"(b1v))

__device__ __forceinline__ uint32_t swz128(uint32_t o) {  // Swizzle<3,4,3>
    return o ^ ((o >> 3) & 0x70u);
}
__device__ __forceinline__ float ex2f(float x) {
    float y; asm("ex2.approx.ftz.f32 %0, %1;" : "=f"(y) : "f"(x)); return y;
}
__device__ __forceinline__ uint32_t h2bits(__half2 h) {
    return *reinterpret_cast<uint32_t*>(&h);
}

// ===================================================================
// fused split: fp32 -> fp16 hi
// ===================================================================
struct SplitJob { const float* src; __half* hi; int nblk; };
struct SplitJobs { SplitJob j[7]; };

__global__ __launch_bounds__(256)
void split_all(const SplitJobs J)
{
    SplitJob jb = J.j[blockIdx.y];
    if ((int)blockIdx.x >= jb.nblk) return;
    int i = (blockIdx.x * 256 + threadIdx.x) * 4;
    float4 v = *(const float4*)(jb.src + i);
    __half2 h01 = __floats2half2_rn(v.x, v.y);
    __half2 h23 = __floats2half2_rn(v.z, v.w);
    uint2 hv = make_uint2(h2bits(h01), h2bits(h23));
    *(uint2*)(jb.hi + i) = hv;
}

// ===================================================================
// GEMM (NT, fp16): C = A(hi) @ Wh^T + bias
// 128x64x64 CTA tile, 4-stage TMA, 2 CTAs/SM. Stage = Ah(16K)+Wh(8K).
// ===================================================================
#define GK      1024
#define GN      1024
#define GBN     64
#define GBK     64
#define GNK     (GK/GBK)
#define GS      4
#define TILE_A  16384
#define TILE_W  8192
#define STAGE_B (TILE_A + TILE_W)     // 24576
#define GEMM_SMEM (GS*STAGE_B + 1024) // 99328

struct QkvMaps {
    CUtensorMap aH[3];
    CUtensorMap wH[3];
};

__device__ __forceinline__ void gemm_mainloop(
    const CUtensorMap* tA, const CUtensorMap* tB,
    int bm, int bn, uint32_t tile0, uint32_t full0, uint32_t emt0,
    int tid, int lane, float acc[2][4][4],
    uint32_t aOffBase, uint32_t bOffBase)
{
    if (tid == 0) {
#pragma unroll
        for (int s = 0; s < GS; s++) {
            uint32_t st = tile0 + s * STAGE_B;
            MBARRIER_EXPECT_TX(full0 + 8 * s, STAGE_B);
            int k0 = s * GBK;
            tma2d(st,          tA, k0, bm, full0 + 8 * s);
            tma2d(st + TILE_A, tB, k0, bn, full0 + 8 * s);
        }
    }

    for (int i = 0; i < GNK; i++) {
        const int s  = i % GS;
        const int ph = (i / GS) & 1;
        MBARRIER_WAIT_PARITY(full0 + 8 * s, ph);

        const uint32_t st = tile0 + s * STAGE_B;
        const uint32_t aH = st;
        const uint32_t bH = st + TILE_A;

#pragma unroll
        for (int ks = 0; ks < 4; ks++) {
            const uint32_t kb = (uint32_t)ks * 32;
            uint32_t ah[2][4];
#pragma unroll
            for (int sub = 0; sub < 2; sub++) {
                uint32_t off = swz128(aOffBase + (uint32_t)sub * 16 * 128 + kb);
                LDSM4(ah[sub], aH + off);
            }
            uint32_t bh[2][4];
#pragma unroll
            for (int nb = 0; nb < 2; nb++) {
                uint32_t off = swz128(bOffBase + (uint32_t)nb * 16 * 128 + kb);
                LDSM4(bh[nb], bH + off);
            }
            MMA16816(acc[0][0], ah[0], bh[0][0], bh[0][1]);
            MMA16816(acc[0][1], ah[0], bh[0][2], bh[0][3]);
            MMA16816(acc[0][2], ah[0], bh[1][0], bh[1][1]);
            MMA16816(acc[0][3], ah[0], bh[1][2], bh[1][3]);
            MMA16816(acc[1][0], ah[1], bh[0][0], bh[0][1]);
            MMA16816(acc[1][1], ah[1], bh[0][2], bh[0][3]);
            MMA16816(acc[1][2], ah[1], bh[1][0], bh[1][1]);
            MMA16816(acc[1][3], ah[1], bh[1][2], bh[1][3]);
        }
        if (lane == 0) MBARRIER_ARRIVE(emt0 + 8 * s);

        if (i + GS < GNK && tid == 0) {
            MBARRIER_WAIT_PARITY(emt0 + 8 * s, ph);
            MBARRIER_EXPECT_TX(full0 + 8 * s, STAGE_B);
            int k0 = (i + GS) * GBK;
            tma2d(st,          tA, k0, bm, full0 + 8 * s);
            tma2d(st + TILE_A, tB, k0, bn, full0 + 8 * s);
        }
    }
}

// fused QKV projection -> fp16 hi outputs
__global__ __launch_bounds__(256, 2)
void gemm_qkv(const __grid_constant__ QkvMaps M,
              const float* __restrict__ bq, const float* __restrict__ bk,
              const float* __restrict__ bv,
              __half* __restrict__ Qh, __half* __restrict__ Kh,
              __half* __restrict__ Vh)
{
    extern __shared__ uint8_t dsm[];
    __shared__ __align__(8) ull s_mbar[2 * GS];

    const int tid  = threadIdx.x;
    const int wid  = tid >> 5;
    const int lane = tid & 31;
    const int wm   = wid & 3;
    const int wn   = wid >> 2;
    const int bm   = blockIdx.y * 128;
    const int bn   = blockIdx.x * GBN;
    const int z    = blockIdx.z;

    const float* bias = (z == 0) ? bq : (z == 1) ? bk : bv;
    __half* Ch = (z == 0) ? Qh : (z == 1) ? Kh : Vh;

    const uint32_t tile0 = (smem_u32(dsm) + 1023u) & ~1023u;
    const uint32_t mb    = smem_u32(s_mbar);
    const uint32_t full0 = mb;
    const uint32_t emt0  = mb + 8 * GS;

    if (tid == 0) {
        for (int s = 0; s < GS; s++) {
            MBARRIER_INIT(full0 + 8 * s, 1);
            MBARRIER_INIT(emt0 + 8 * s, 8);
        }
    }
    __syncthreads();

    float acc[2][4][4];
#pragma unroll
    for (int i = 0; i < 2; i++)
#pragma unroll
        for (int j = 0; j < 4; j++)
#pragma unroll
            for (int q = 0; q < 4; q++) acc[i][j][q] = 0.0f;

    const int aRow = wm * 32 + (lane & 7) + ((lane >> 3) & 1) * 8;
    const uint32_t aOffBase = (uint32_t)aRow * 128 + ((lane >> 4) & 1) * 16;
    const int bRow = wn * 32 + (lane & 7) + ((lane >> 4) & 1) * 8;
    const uint32_t bOffBase = (uint32_t)bRow * 128 + ((lane >> 3) & 1) * 16;

    gemm_mainloop(&M.aH[z], &M.wH[z],
                  bm, bn, tile0, full0, emt0, tid, lane, acc, aOffBase, bOffBase);

    const int r0 = bm + wm * 32 + (lane >> 2);
    const int c0 = bn + wn * 32 + (lane & 3) * 2;
#pragma unroll
    for (int sub = 0; sub < 2; sub++) {
#pragma unroll
        for (int nb = 0; nb < 4; nb++) {
            int row = r0 + sub * 16;
            int col = c0 + nb * 8;
            float2 bv2 = *(const float2*)(bias + col);
            __half2 h0 = __floats2half2_rn(acc[sub][nb][0] + bv2.x, acc[sub][nb][1] + bv2.y);
            __half2 h1 = __floats2half2_rn(acc[sub][nb][2] + bv2.x, acc[sub][nb][3] + bv2.y);
            *(uint32_t*)(Ch + (size_t)row * GN + col)       = h2bits(h0);
            *(uint32_t*)(Ch + (size_t)(row + 8) * GN + col) = h2bits(h1);
        }
    }
}

// output projection: A = ctx hi, B = WOh; fp32 epilogue
__global__ __launch_bounds__(256, 2)
void gemm_out(const __grid_constant__ CUtensorMap tmA,
              const __grid_constant__ CUtensorMap tmB,
              const float* __restrict__ bias, float* __restrict__ Cf)
{
    extern __shared__ uint8_t dsm[];
    __shared__ __align__(8) ull s_mbar[2 * GS];

    const int tid  = threadIdx.x;
    const int wid  = tid >> 5;
    const int lane = tid & 31;
    const int wm   = wid & 3;
    const int wn   = wid >> 2;
    const int bm   = blockIdx.y * 128;
    const int bn   = blockIdx.x * GBN;

    const uint32_t tile0 = (smem_u32(dsm) + 1023u) & ~1023u;
    const uint32_t mb    = smem_u32(s_mbar);
    const uint32_t full0 = mb;
    const uint32_t emt0  = mb + 8 * GS;

    if (tid == 0) {
        for (int s = 0; s < GS; s++) {
            MBARRIER_INIT(full0 + 8 * s, 1);
            MBARRIER_INIT(emt0 + 8 * s, 8);
        }
    }
    __syncthreads();

    float acc[2][4][4];
#pragma unroll
    for (int i = 0; i < 2; i++)
#pragma unroll
        for (int j = 0; j < 4; j++)
#pragma unroll
            for (int q = 0; q < 4; q++) acc[i][j][q] = 0.0f;

    const int aRow = wm * 32 + (lane & 7) + ((lane >> 3) & 1) * 8;
    const uint32_t aOffBase = (uint32_t)aRow * 128 + ((lane >> 4) & 1) * 16;
    const int bRow = wn * 32 + (lane & 7) + ((lane >> 4) & 1) * 8;
    const uint32_t bOffBase = (uint32_t)bRow * 128 + ((lane >> 3) & 1) * 16;

    gemm_mainloop(&tmA, &tmB,
                  bm, bn, tile0, full0, emt0, tid, lane, acc, aOffBase, bOffBase);

    const int r0 = bm + wm * 32 + (lane >> 2);
    const int c0 = bn + wn * 32 + (lane & 3) * 2;
#pragma unroll
    for (int sub = 0; sub < 2; sub++) {
#pragma unroll
        for (int nb = 0; nb < 4; nb++) {
            int row = r0 + sub * 16;
            int col = c0 + nb * 8;
            float2 bv2 = *(const float2*)(bias + col);
            *(float2*)(Cf + (size_t)row * GN + col) =
                make_float2(acc[sub][nb][0] + bv2.x, acc[sub][nb][1] + bv2.y);
            *(float2*)(Cf + (size_t)(row + 8) * GN + col) =
                make_float2(acc[sub][nb][2] + bv2.x, acc[sub][nb][3] + bv2.y);
        }
    }
}

// ===================================================================
// Causal flash attention, pure fp16 (1-pass): S = Qh·Kh; O = Ph·Vh.
// 128-key tiles, 3-stage TMA (stage = Kh+Vh = 32KB).
// ===================================================================
#define FSTG 3
#define FT_B 16384
#define FST_B (2*FT_B)
#define FLASH_SMEM (FSTG*FST_B + 1024)
#define C1F 0.18033688011112042f   // log2(e)/8

__global__ __launch_bounds__(256)
void flash_mma(const __grid_constant__ CUtensorMap tmQh,
               const __grid_constant__ CUtensorMap tmKh,
               const __grid_constant__ CUtensorMap tmVh,
               __half* __restrict__ Oh)
{
    extern __shared__ uint8_t dsm[];
    __shared__ __align__(8) ull s_mbar[2 * FSTG + 1];

    const int tid  = threadIdx.x;
    const int wid  = tid >> 5;
    const int lane = tid & 31;
    const int qt   = (int)gridDim.x - 1 - (int)blockIdx.x;
    const int h    = blockIdx.y;
    const int b    = blockIdx.z;
    const int q0   = qt * 128;
    const int nkt  = qt + 1;
    const int xoff = h * HDIM;
    const int yb   = b * SEQ;

    const uint32_t tile0 = (smem_u32(dsm) + 1023u) & ~1023u;
    const uint32_t mb    = smem_u32(s_mbar);
    const uint32_t full0 = mb;
    const uint32_t emt0  = mb + 8 * FSTG;
    const uint32_t qbar  = mb + 16 * FSTG;

    if (tid == 0) {
        for (int s = 0; s < FSTG; s++) {
            MBARRIER_INIT(full0 + 8 * s, 1);
            MBARRIER_INIT(emt0 + 8 * s, 8);
        }
        MBARRIER_INIT(qbar, 1);
        MBARRIER_EXPECT_TX(qbar, FT_B);
        tma2d(tile0, &tmQh, xoff, yb + q0, qbar);
    }
    __syncthreads();
    MBARRIER_WAIT_PARITY(qbar, 0);

    // Q fragments (persist in registers)
    const uint32_t aOff = (uint32_t)(wid * 16 + (lane & 7) + ((lane >> 3) & 1) * 8) * 128
                        + ((lane >> 4) & 1) * 16;
    uint32_t qh[4][4];
#pragma unroll
    for (int kb = 0; kb < 4; kb++) {
        uint32_t off = swz128(aOff + kb * 32);
        LDSM4(qh[kb], tile0 + off);
    }
    __syncthreads();   // Q reads done before K/V TMA reuses stage area

    if (tid == 0) {
        int npre = nkt < FSTG ? nkt : FSTG;
        for (int p = 0; p < npre; p++) {
            uint32_t st = tile0 + p * FST_B;
            MBARRIER_EXPECT_TX(full0 + 8 * p, FST_B);
            int y = yb + p * 128;
            tma2d(st,        &tmKh, xoff, y, full0 + 8 * p);
            tma2d(st + FT_B, &tmVh, xoff, y, full0 + 8 * p);
        }
    }

    float m0 = -1e30f, m1 = -1e30f, l0 = 0.0f, l1 = 0.0f;
    float oacc[8][4];
#pragma unroll
    for (int i = 0; i < 8; i++)
#pragma unroll
        for (int j = 0; j < 4; j++) oacc[i][j] = 0.0f;

    const uint32_t kOff = (uint32_t)((lane & 7) + ((lane >> 4) & 1) * 8) * 128
                        + ((lane >> 3) & 1) * 16;
    const uint32_t vOff = (uint32_t)((lane & 7) + ((lane >> 3) & 1) * 8) * 128
                        + ((lane >> 4) & 1) * 16;
    const int qrow = wid * 16 + (lane >> 2);
    const int nbLim  = 2 * wid + 1;
    const int nb2Lim = wid;

    for (int kt = 0; kt < nkt; kt++) {
        const int s  = kt % FSTG;
        const int ph = (kt / FSTG) & 1;
        const bool diag = (kt == qt);
        MBARRIER_WAIT_PARITY(full0 + 8 * s, ph);
        const uint32_t stb = tile0 + s * FST_B;

        float sc[16][4];
#pragma unroll
        for (int i = 0; i < 16; i++)
#pragma unroll
            for (int j = 0; j < 4; j++) sc[i][j] = 0.0f;

        // ---- S = Qh·Kh : groups of 4 nb2, 8 independent accumulators ----
#pragma unroll
        for (int kb = 0; kb < 4; kb++) {
#pragma unroll
            for (int g = 0; g < 2; g++) {
                if (diag && g * 4 > nb2Lim) break;
                uint32_t bh[4][4];
#pragma unroll
                for (int j = 0; j < 4; j++) {
                    int nb2 = g * 4 + j;
                    if (diag && nb2 > nb2Lim) continue;
                    uint32_t off = swz128(kOff + (uint32_t)nb2 * 2048 + (uint32_t)kb * 32);
                    LDSM4(bh[j], stb + off);
                }
#pragma unroll
                for (int j = 0; j < 4; j++) {
                    int nb2 = g * 4 + j;
                    if (diag && nb2 > nb2Lim) continue;
                    MMA16816(sc[2 * nb2],     qh[kb], bh[j][0], bh[j][1]);
                    MMA16816(sc[2 * nb2 + 1], qh[kb], bh[j][2], bh[j][3]);
                }
            }
        }

#pragma unroll
        for (int nb = 0; nb < 16; nb++) {
            if (diag && nb > nbLim) break;
#pragma unroll
            for (int j = 0; j < 4; j++) sc[nb][j] *= C1F;
        }

        if (diag) {
#pragma unroll
            for (int nb = 0; nb < 16; nb++) {
                if (nb > nbLim) break;
                int c = nb * 8 + (lane & 3) * 2;
                if (c     > qrow)     sc[nb][0] = -1e30f;
                if (c + 1 > qrow)     sc[nb][1] = -1e30f;
                if (c     > qrow + 8) sc[nb][2] = -1e30f;
                if (c + 1 > qrow + 8) sc[nb][3] = -1e30f;
            }
        }

        float mx0 = -1e30f, mx1 = -1e30f;
#pragma unroll
        for (int nb = 0; nb < 16; nb++) {
            if (diag && nb > nbLim) break;
            mx0 = fmaxf(mx0, fmaxf(sc[nb][0], sc[nb][1]));
            mx1 = fmaxf(mx1, fmaxf(sc[nb][2], sc[nb][3]));
        }
        mx0 = fmaxf(mx0, __shfl_xor_sync(0xffffffffu, mx0, 1));
        mx0 = fmaxf(mx0, __shfl_xor_sync(0xffffffffu, mx0, 2));
        mx1 = fmaxf(mx1, __shfl_xor_sync(0xffffffffu, mx1, 1));
        mx1 = fmaxf(mx1, __shfl_xor_sync(0xffffffffu, mx1, 2));
        float mn0 = fmaxf(m0, mx0), mn1 = fmaxf(m1, mx1);
        float cor0 = ex2f(m0 - mn0), cor1 = ex2f(m1 - mn1);
        m0 = mn0; m1 = mn1;
        float su0 = 0.0f, su1 = 0.0f;
#pragma unroll
        for (int nb = 0; nb < 16; nb++) {
            if (diag && nb > nbLim) break;
            sc[nb][0] = ex2f(sc[nb][0] - mn0); su0 += sc[nb][0];
            sc[nb][1] = ex2f(sc[nb][1] - mn0); su0 += sc[nb][1];
            sc[nb][2] = ex2f(sc[nb][2] - mn1); su1 += sc[nb][2];
            sc[nb][3] = ex2f(sc[nb][3] - mn1); su1 += sc[nb][3];
        }
        su0 += __shfl_xor_sync(0xffffffffu, su0, 1);
        su0 += __shfl_xor_sync(0xffffffffu, su0, 2);
        su1 += __shfl_xor_sync(0xffffffffu, su1, 1);
        su1 += __shfl_xor_sync(0xffffffffu, su1, 2);
        l0 = l0 * cor0 + su0;
        l1 = l1 * cor1 + su1;
#pragma unroll
        for (int nb = 0; nb < 8; nb++) {
            oacc[nb][0] *= cor0; oacc[nb][1] *= cor0;
            oacc[nb][2] *= cor1; oacc[nb][3] *= cor1;
        }

        // ---- O += Ph·Vh : per kb2, 8 independent accumulators ----
#pragma unroll
        for (int kb2 = 0; kb2 < 8; kb2++) {
            if (diag && kb2 > nb2Lim) break;
            const float* p0 = sc[2 * kb2];
            const float* p1 = sc[2 * kb2 + 1];
            uint32_t aph[4];
            aph[0] = h2bits(__floats2half2_rn(p0[0], p0[1]));
            aph[1] = h2bits(__floats2half2_rn(p0[2], p0[3]));
            aph[2] = h2bits(__floats2half2_rn(p1[0], p1[1]));
            aph[3] = h2bits(__floats2half2_rn(p1[2], p1[3]));
            uint32_t vh[4][4];
#pragma unroll
            for (int db2 = 0; db2 < 4; db2++) {
                uint32_t off = swz128(vOff + (uint32_t)kb2 * 2048 + (uint32_t)db2 * 32);
                LDSM4T(vh[db2], stb + FT_B + off);
            }
#pragma unroll
            for (int db2 = 0; db2 < 4; db2++) {
                MMA16816(oacc[2 * db2],     aph, vh[db2][0], vh[db2][1]);
                MMA16816(oacc[2 * db2 + 1], aph, vh[db2][2], vh[db2][3]);
            }
        }

        __syncwarp();
        if (lane == 0) MBARRIER_ARRIVE(emt0 + 8 * s);
        if (kt + FSTG < nkt && tid == 0) {
            MBARRIER_WAIT_PARITY(emt0 + 8 * s, ph);
            MBARRIER_EXPECT_TX(full0 + 8 * s, FST_B);
            int y = yb + (kt + FSTG) * 128;
            tma2d(stb,        &tmKh, xoff, y, full0 + 8 * s);
            tma2d(stb + FT_B, &tmVh, xoff, y, full0 + 8 * s);
        }
    }

    float inv0 = 1.0f / l0, inv1 = 1.0f / l1;
    const size_t row0 = (size_t)(yb + q0 + wid * 16 + (lane >> 2));
    const int colb = xoff + (lane & 3) * 2;
#pragma unroll
    for (int nb = 0; nb < 8; nb++) {
        int c = colb + nb * 8;
        __half2 h0 = __floats2half2_rn(oacc[nb][0] * inv0, oacc[nb][1] * inv0);
        __half2 h1 = __floats2half2_rn(oacc[nb][2] * inv1, oacc[nb][3] * inv1);
        *(uint32_t*)(Oh + row0 * EMBED + c)       = h2bits(h0);
        *(uint32_t*)(Oh + (row0 + 8) * EMBED + c) = h2bits(h1);
    }
}

// ===================================================================
// host
// ===================================================================
typedef CUresult (*PFN_tmap)(CUtensorMap*, CUtensorMapDataType, cuuint32_t, void*,
                             const cuuint64_t*, const cuuint64_t*, const cuuint32_t*,
                             const cuuint32_t*, CUtensorMapInterleave, CUtensorMapSwizzle,
                             CUtensorMapL2promotion, CUtensorMapFloatOOBfill);

static void make_map2d(PFN_tmap fn, CUtensorMap* m, void* base, int rows, int boxRows) {
    cuuint64_t dims[2]    = {(cuuint64_t)EMBED, (cuuint64_t)rows};
    cuuint64_t strides[1] = {(cuuint64_t)EMBED * 2};
    cuuint32_t box[2]     = {64u, (cuuint32_t)boxRows};
    cuuint32_t estr[2]    = {1u, 1u};
    fn(m, CU_TENSOR_MAP_DATA_TYPE_FLOAT16, 2, base, dims, strides, box, estr,
       CU_TENSOR_MAP_INTERLEAVE_NONE, CU_TENSOR_MAP_SWIZZLE_128B,
       CU_TENSOR_MAP_L2_PROMOTION_L2_128B, CU_TENSOR_MAP_FLOAT_OOB_FILL_NONE);
}

extern "C" void kernel_launch(void* const* d_in, const int* in_sizes, int n_in,
                              void* d_out, int out_size)
{
    (void)in_sizes; (void)n_in; (void)out_size;
    const float* query = (const float*)d_in[0];
    const float* key   = (const float*)d_in[1];
    const float* value = (const float*)d_in[2];
    // d_in[3]: causal mask — analytically tril, applied in-kernel.
    const float* Wq = (const float*)d_in[4];
    const float* bq = (const float*)d_in[5];
    const float* Wk = (const float*)d_in[6];
    const float* bk = (const float*)d_in[7];
    const float* Wv = (const float*)d_in[8];
    const float* bv = (const float*)d_in[9];
    const float* Wo = (const float*)d_in[10];
    const float* bo = (const float*)d_in[11];
    float* out = (float*)d_out;

    __half *pAQh, *pAKh, *pAVh, *pQh, *pKh, *pVh;
    __half *pWQh, *pWKh, *pWVh, *pWOh;
    cudaGetSymbolAddress((void**)&pAQh, g_AQh);
    cudaGetSymbolAddress((void**)&pAKh, g_AKh);
    cudaGetSymbolAddress((void**)&pAVh, g_AVh);
    cudaGetSymbolAddress((void**)&pQh, g_Qh);
    cudaGetSymbolAddress((void**)&pKh, g_Kh);
    cudaGetSymbolAddress((void**)&pVh, g_Vh);
    cudaGetSymbolAddress((void**)&pWQh, g_WQh);
    cudaGetSymbolAddress((void**)&pWKh, g_WKh);
    cudaGetSymbolAddress((void**)&pWVh, g_WVh);
    cudaGetSymbolAddress((void**)&pWOh, g_WOh);

    static PFN_tmap pfn = nullptr;
    if (!pfn) {
        cudaDriverEntryPointQueryResult st;
        cudaGetDriverEntryPointByVersion("cuTensorMapEncodeTiled", (void**)&pfn,
                                         12000, cudaEnableDefault, &st);
    }

    QkvMaps qm;
    make_map2d(pfn, &qm.aH[0], pAQh, NTOK, 128);
    make_map2d(pfn, &qm.aH[1], pAKh, NTOK, 128);
    make_map2d(pfn, &qm.aH[2], pAVh, NTOK, 128);
    make_map2d(pfn, &qm.wH[0], pWQh, EMBED, 64);
    make_map2d(pfn, &qm.wH[1], pWKh, EMBED, 64);
    make_map2d(pfn, &qm.wH[2], pWVh, EMBED, 64);

    CUtensorMap mQh, mKh, mVh, mCh, mWOh;
    make_map2d(pfn, &mQh, pQh, NTOK, 128);
    make_map2d(pfn, &mKh, pKh, NTOK, 128);
    make_map2d(pfn, &mVh, pVh, NTOK, 128);
    make_map2d(pfn, &mCh, pAQh, NTOK, 128);   // ctx reuses act-Q hi buffer
    make_map2d(pfn, &mWOh, pWOh, EMBED, 64);

    static bool attr_done = false;
    if (!attr_done) {
        cudaFuncSetAttribute(gemm_qkv, cudaFuncAttributeMaxDynamicSharedMemorySize, GEMM_SMEM);
        cudaFuncSetAttribute(gemm_out, cudaFuncAttributeMaxDynamicSharedMemorySize, GEMM_SMEM);
        cudaFuncSetAttribute(flash_mma, cudaFuncAttributeMaxDynamicSharedMemorySize, FLASH_SMEM);
        attr_done = true;
    }

    const int actBlocks = (NTOK * EMBED) / (256 * 4);   // 4096
    const int wBlocks   = (EMBED * EMBED) / (256 * 4);  // 1024

    SplitJobs J;
    J.j[0] = { query, pAQh, actBlocks };
    J.j[1] = { key,   pAKh, actBlocks };
    J.j[2] = { value, pAVh, actBlocks };
    J.j[3] = { Wq,    pWQh, wBlocks };
    J.j[4] = { Wk,    pWKh, wBlocks };
    J.j[5] = { Wv,    pWVh, wBlocks };
    J.j[6] = { Wo,    pWOh, wBlocks };

    dim3 gs(actBlocks, 7);
    split_all<<<gs, 256>>>(J);

    dim3 gq(GN / GBN, NTOK / 128, 3);   // (16, 32, 3) = 1536 CTAs
    gemm_qkv<<<gq, 256, GEMM_SMEM>>>(qm, bq, bk, bv, pQh, pKh, pVh);

    dim3 ga(SEQ / 128, HEADS, BSZ);     // (16, 16, 2)
    flash_mma<<<ga, 256, FLASH_SMEM>>>(mQh, mKh, mVh, pAQh);

    dim3 go(GN / GBN, NTOK / 128);      // (16, 32) = 512 CTAs
    gemm_out<<<go, 256, GEMM_SMEM>>>(mCh, mWOh, bo, out);
}